// round 9
// baseline (speedup 1.0000x reference)
#include <cuda_runtime.h>
#include <cuda_bf16.h>
#include <cstdint>

#define BB   4
#define N1   16384
#define N2   4096
#define C1   128
#define C2   256
#define M1   256
#define M2   128
#define NTOT 65536
#define EPS_BN 1e-5f

// K-stacked bf16 operand layouts (hi | lo)
#define X1ROW 768
#define W1ROW 768
#define X2ROW 512
#define W2ROW 512

// ---------------- scratch (static device globals) ----------------
__device__ __nv_bfloat16 g_X1[(size_t)NTOT * X1ROW];
__device__ __nv_bfloat16 g_X2[(size_t)NTOT * X2ROW];
__device__ __nv_bfloat16 g_W1s[M1 * W1ROW];
__device__ __nv_bfloat16 g_W2s[M2 * W2ROW];
__device__ float g_Y1[(size_t)NTOT * M1];
__device__ float g_p2t[BB * N2 * C2];
__device__ float4 g_s2[BB * N2];                      // norm-sorted (x,y,z,|p|) per batch
__device__ int   g_sidx[BB * N2];                     // sorted-pos -> original index
__device__ int   g_i0[NTOT], g_i1[NTOT], g_i2[NTOT];
__device__ float g_w0[NTOT], g_w1[NTOT], g_w2[NTOT];
__device__ float g_sum1[M1], g_sq1[M1], g_scale1[M1], g_shift1[M1];
__device__ float g_sum2[M2], g_sq2[M2], g_scale2[M2], g_shift2[M2];

// ---------------- helpers ----------------
__device__ __forceinline__ uint32_t smem_u32(const void* p) {
    uint32_t a;
    asm("{ .reg .u64 t; cvta.to.shared.u64 t, %1; cvt.u32.u64 %0, t; }" : "=r"(a) : "l"(p));
    return a;
}
#define CP16(dst, src) \
    asm volatile("cp.async.cg.shared.global [%0], [%1], 16;" :: "r"(dst), "l"(src) : "memory")
#define CPCOMMIT() asm volatile("cp.async.commit_group;" ::: "memory")
#define CPWAIT0()  asm volatile("cp.async.wait_group 0;" ::: "memory")

#define LDM4(r, addr) \
    asm volatile("ldmatrix.sync.aligned.m8n8.x4.shared.b16 {%0,%1,%2,%3}, [%4];" \
        : "=r"((r)[0]), "=r"((r)[1]), "=r"((r)[2]), "=r"((r)[3]) : "r"(addr))

#define MMA(d, a, b0, b1) \
    asm volatile("mma.sync.aligned.m16n8k16.row.col.f32.bf16.bf16.f32 " \
        "{%0,%1,%2,%3},{%4,%5,%6,%7},{%8,%9},{%0,%1,%2,%3};" \
        : "+f"((d)[0]), "+f"((d)[1]), "+f"((d)[2]), "+f"((d)[3]) \
        : "r"((a)[0]), "r"((a)[1]), "r"((a)[2]), "r"((a)[3]), "r"(b0), "r"(b1))

__device__ __forceinline__ __nv_bfloat16 bhi(float x) { return __float2bfloat16(x); }
__device__ __forceinline__ __nv_bfloat16 blo(float x, __nv_bfloat16 h) {
    return __float2bfloat16(x - __bfloat162float(h));
}

#define ROWB   80
#define TILEB  10240
#define STAGEB 20480
#define SMEM_DYN 40960   // 2 mainloop stages; gemm2 epilogue uses 64x136x4=34816

// ---------------- init ----------------
__global__ void init_kernel() {
    int t = threadIdx.x;
    if (t < M1) { g_sum1[t] = 0.f; g_sq1[t] = 0.f; }
    if (t < M2) { g_sum2[t] = 0.f; g_sq2[t] = 0.f; }
}

// ---------------- transpose points2 (B,C2,N2) -> (B,N2,C2) ----------------
__global__ void transpose_p2_kernel(const float* __restrict__ p2) {
    __shared__ float tile[32][33];
    int b = blockIdx.z, n0 = blockIdx.x * 32, c0 = blockIdx.y * 32;
    const float* src = p2 + (size_t)b * C2 * N2;
    #pragma unroll
    for (int i = 0; i < 32; i += 8)
        tile[threadIdx.y + i][threadIdx.x] = src[(size_t)(c0 + threadIdx.y + i) * N2 + n0 + threadIdx.x];
    __syncthreads();
    float* dst = g_p2t + (size_t)b * N2 * C2;
    #pragma unroll
    for (int i = 0; i < 32; i += 8)
        dst[(size_t)(n0 + threadIdx.y + i) * C2 + c0 + threadIdx.x] = tile[threadIdx.x][threadIdx.y + i];
}

// ---------------- W hi/lo prep ----------------
__global__ void cvt_w_kernel(const float* __restrict__ W1, const float* __restrict__ W2) {
    int i = blockIdx.x * 256 + threadIdx.x;
    if (i < M1 * 384) {
        int r = i / 384, c = i % 384;
        float w = W1[i];
        __nv_bfloat16 h = bhi(w);
        g_W1s[r * W1ROW + c] = h;
        g_W1s[r * W1ROW + 384 + c] = blo(w, h);
    }
    if (i < M2 * 256) {
        int r = i / 256, c = i % 256;
        float w = W2[i];
        __nv_bfloat16 h = bhi(w);
        g_W2s[r * W2ROW + c] = h;
        g_W2s[r * W2ROW + 256 + c] = blo(w, h);
    }
}

// ---------------- points1 -> X1 cols[0..127]=hi, [384..511]=lo ----------------
__global__ void cvt_p1_kernel(const float* __restrict__ points1) {
    __shared__ float tile[32][33];
    int b = blockIdx.z, n0 = blockIdx.x * 32, c0 = blockIdx.y * 32;
    int tx = threadIdx.x & 31, ty = threadIdx.x >> 5;
    const float* src = points1 + (size_t)b * C1 * N1;
    #pragma unroll
    for (int i = 0; i < 32; i += 8)
        tile[ty + i][tx] = src[(size_t)(c0 + ty + i) * N1 + n0 + tx];
    __syncthreads();
    int p = threadIdx.x >> 3, g = threadIdx.x & 7;
    float f0 = tile[g * 4 + 0][p], f1 = tile[g * 4 + 1][p];
    float f2 = tile[g * 4 + 2][p], f3 = tile[g * 4 + 3][p];
    __nv_bfloat16 h0 = bhi(f0), h1 = bhi(f1), h2 = bhi(f2), h3 = bhi(f3);
    size_t row = (size_t)(b * N1 + n0 + p) * X1ROW;
    __nv_bfloat162 v;
    v.x = h0; v.y = h1; *(__nv_bfloat162*)&g_X1[row + c0 + g * 4] = v;
    v.x = h2; v.y = h3; *(__nv_bfloat162*)&g_X1[row + c0 + g * 4 + 2] = v;
    v.x = blo(f0, h0); v.y = blo(f1, h1); *(__nv_bfloat162*)&g_X1[row + 384 + c0 + g * 4] = v;
    v.x = blo(f2, h2); v.y = blo(f3, h3); *(__nv_bfloat162*)&g_X1[row + 384 + c0 + g * 4 + 2] = v;
}

// ---------------- sort points2 by norm (bitonic, one block per batch) ----------------
__global__ __launch_bounds__(1024) void sort_kernel(const float* __restrict__ xyz2) {
    __shared__ float k[N2];
    __shared__ int   v[N2];
    int b = blockIdx.x, tid = threadIdx.x;
    const float* x2 = xyz2 + (size_t)b * 3 * N2;
    for (int i = tid; i < N2; i += 1024) {
        float px = x2[i], py = x2[N2 + i], pz = x2[2 * N2 + i];
        k[i] = sqrtf(px * px + py * py + pz * pz);
        v[i] = i;
    }
    __syncthreads();
    for (int ksz = 2; ksz <= N2; ksz <<= 1) {
        for (int j = ksz >> 1; j > 0; j >>= 1) {
            for (int i = tid; i < N2; i += 1024) {
                int ixj = i ^ j;
                if (ixj > i) {
                    bool up = (i & ksz) == 0;
                    float a = k[i], c = k[ixj];
                    if ((a > c) == up) {
                        k[i] = c; k[ixj] = a;
                        int t = v[i]; v[i] = v[ixj]; v[ixj] = t;
                    }
                }
            }
            __syncthreads();
        }
    }
    for (int i = tid; i < N2; i += 1024) {
        int oi = v[i];
        g_s2[b * N2 + i] = make_float4(x2[oi], x2[N2 + oi], x2[2 * N2 + oi], k[i]);
        g_sidx[b * N2 + i] = oi;
    }
}

// ---------------- 3-NN with exact norm pruning ----------------
__global__ void knn_pruned_kernel(const float* __restrict__ xyz1) {
    int b = blockIdx.y;
    int n = blockIdx.x * 256 + threadIdx.x;
    const float* x1 = xyz1 + (size_t)b * 3 * N1;
    float qx = x1[n], qy = x1[N1 + n], qz = x1[2 * N1 + n];
    float s1 = qx * qx + qy * qy + qz * qz;
    float nq = sqrtf(s1);
    float m2x = -2.0f * qx, m2y = -2.0f * qy, m2z = -2.0f * qz;
    const float4* S = g_s2 + (size_t)b * N2;

    int lo = 0, hi = N2;
    while (lo < hi) {
        int mid = (lo + hi) >> 1;
        if (S[mid].w < nq) lo = mid + 1; else hi = mid;
    }
    int L = lo - 1, R = lo;
    float d0 = 3.4e38f, d1 = 3.4e38f, d2 = 3.4e38f;
    int   p0 = 0, p1 = 0, p2 = 0;
    bool aL = (L >= 0), aR = (R < N2);

    while (__ballot_sync(0xffffffffu, aL || aR)) {
        if (aL) {
            float4 f = S[L];
            float t = f.w - nq;
            if (t * t > d2) aL = false;
            else {
                float d = fmaf(f.w, f.w, fmaf(m2x, f.x, fmaf(m2y, f.y, fmaf(m2z, f.z, s1))));
                if (d < d2) {
                    if (d < d1) {
                        d2 = d1; p2 = p1;
                        if (d < d0) { d1 = d0; p1 = p0; d0 = d; p0 = L; }
                        else        { d1 = d;  p1 = L; }
                    } else { d2 = d; p2 = L; }
                }
                if (--L < 0) aL = false;
            }
        }
        if (aR) {
            float4 f = S[R];
            float t = f.w - nq;
            if (t * t > d2) aR = false;
            else {
                float d = fmaf(f.w, f.w, fmaf(m2x, f.x, fmaf(m2y, f.y, fmaf(m2z, f.z, s1))));
                if (d < d2) {
                    if (d < d1) {
                        d2 = d1; p2 = p1;
                        if (d < d0) { d1 = d0; p1 = p0; d0 = d; p0 = R; }
                        else        { d1 = d;  p1 = R; }
                    } else { d2 = d; p2 = R; }
                }
                if (++R >= N2) aR = false;
            }
        }
    }

    // exact squared dists (reference formula) -> weights
    float4 f0 = S[p0], f1 = S[p1], f2 = S[p2];
    float w[3];
    {
        float dx = qx - f0.x, dy = qy - f0.y, dz = qz - f0.z;
        w[0] = 1.0f / fmaxf(dx * dx + dy * dy + dz * dz, 1e-10f);
    }
    {
        float dx = qx - f1.x, dy = qy - f1.y, dz = qz - f1.z;
        w[1] = 1.0f / fmaxf(dx * dx + dy * dy + dz * dz, 1e-10f);
    }
    {
        float dx = qx - f2.x, dy = qy - f2.y, dz = qz - f2.z;
        w[2] = 1.0f / fmaxf(dx * dx + dy * dy + dz * dz, 1e-10f);
    }
    float ws = w[0] + w[1] + w[2];
    int P = b * N1 + n;
    g_i0[P] = g_sidx[b * N2 + p0];
    g_i1[P] = g_sidx[b * N2 + p1];
    g_i2[P] = g_sidx[b * N2 + p2];
    g_w0[P] = w[0] / ws; g_w1[P] = w[1] / ws; g_w2[P] = w[2] / ws;
}

// ---------------- interp -> X1 cols[128..383]=hi, [512..767]=lo ----------------
__global__ void interp_kernel() {
    int p    = blockIdx.x * 8 + (threadIdx.x >> 5);
    int lane = threadIdx.x & 31;
    int b    = p >> 14;
    float w0 = g_w0[p], w1 = g_w1[p], w2 = g_w2[p];
    const float4* r0 = (const float4*)(g_p2t + ((size_t)b * N2 + g_i0[p]) * C2);
    const float4* r1 = (const float4*)(g_p2t + ((size_t)b * N2 + g_i1[p]) * C2);
    const float4* r2 = (const float4*)(g_p2t + ((size_t)b * N2 + g_i2[p]) * C2);
    size_t row = (size_t)p * X1ROW;
    int cA = lane, cB = lane + 32;
    float4 a0 = r0[cA], e0 = r1[cA], f0 = r2[cA];
    float4 a1 = r0[cB], e1 = r1[cB], f1 = r2[cB];
    #pragma unroll
    for (int it = 0; it < 2; it++) {
        float4 a = it ? a1 : a0, e = it ? e1 : e0, f = it ? f1 : f0;
        int c = it ? cB : cA;
        float ox = w0 * a.x + w1 * e.x + w2 * f.x;
        float oy = w0 * a.y + w1 * e.y + w2 * f.y;
        float oz = w0 * a.z + w1 * e.z + w2 * f.z;
        float ow = w0 * a.w + w1 * e.w + w2 * f.w;
        __nv_bfloat16 h0 = bhi(ox), h1 = bhi(oy), h2 = bhi(oz), h3 = bhi(ow);
        __nv_bfloat162 v;
        v.x = h0; v.y = h1; *(__nv_bfloat162*)&g_X1[row + 128 + 4 * c] = v;
        v.x = h2; v.y = h3; *(__nv_bfloat162*)&g_X1[row + 128 + 4 * c + 2] = v;
        v.x = blo(ox, h0); v.y = blo(oy, h1); *(__nv_bfloat162*)&g_X1[row + 512 + 4 * c] = v;
        v.x = blo(oz, h2); v.y = blo(ow, h3); *(__nv_bfloat162*)&g_X1[row + 512 + 4 * c + 2] = v;
    }
}

// ---------------- shared mainloop piece: one BK=32 chunk of HMMA ----------------
__device__ __forceinline__ void mma_chunk(uint32_t smA, uint32_t smB, int wn, int wm,
                                          int lane, float acc[2][8][4]) {
    uint32_t rsel = (uint32_t)(lane & 15);
    uint32_t csel = (uint32_t)(lane >> 4) * 16;
    #pragma unroll
    for (int ks = 0; ks < 2; ks++) {
        uint32_t af[2][4], bf[4][4];
        #pragma unroll
        for (int t = 0; t < 2; t++)
            LDM4(af[t], smA + (wn * 32 + t * 16 + rsel) * ROWB + ks * 32 + csel);
        #pragma unroll
        for (int jj = 0; jj < 4; jj++)
            LDM4(bf[jj], smB + (wm * 64 + jj * 16 + rsel) * ROWB + ks * 32 + csel);
        #pragma unroll
        for (int t = 0; t < 2; t++)
            #pragma unroll
            for (int j = 0; j < 8; j++)
                MMA(acc[t][j], af[t], bf[j >> 1][(j & 1)], bf[j >> 1][(j & 1) + 2]);
    }
}

// ---------------- GEMM1: Y1[n][m] = sum_k X1[n,k]*W1s[m,k] (HMMA, 3-term) ----------------
__global__ __launch_bounds__(256) void gemm1_tc() {
    extern __shared__ char dsm[];
    uint32_t sb = smem_u32(dsm);
    int tid = threadIdx.x, lane = tid & 31, wid = tid >> 5;
    int wn = wid & 3, wm = wid >> 2;
    int n0 = blockIdx.x * 128, m0 = blockIdx.y * 128;

    const __nv_bfloat16* Xb = g_X1  + (size_t)n0 * X1ROW;
    const __nv_bfloat16* Wb = g_W1s + (size_t)m0 * W1ROW;

    float acc[2][8][4];
    #pragma unroll
    for (int t = 0; t < 2; t++)
        #pragma unroll
        for (int j = 0; j < 8; j++)
            #pragma unroll
            for (int d = 0; d < 4; d++) acc[t][j][d] = 0.f;

    int row2 = tid >> 2, c4 = tid & 3;
    auto load = [&](int i) {
        int s = i & 1;
        int t = i / 12, kc = i % 12;
        int aoff = ((t == 1) ? 384 : 0) + kc * 32;
        int boff = ((t == 2) ? 384 : 0) + kc * 32;
        uint32_t dstA = sb + s * STAGEB;
        uint32_t dstB = dstA + TILEB;
        #pragma unroll
        for (int u = 0; u < 2; u++) {
            int r = row2 + u * 64;
            CP16(dstA + r * ROWB + c4 * 16, Xb + (size_t)r * X1ROW + aoff + c4 * 8);
            CP16(dstB + r * ROWB + c4 * 16, Wb + (size_t)r * W1ROW + boff + c4 * 8);
        }
        CPCOMMIT();
    };

    load(0);
    for (int i = 0; i < 36; i++) {
        CPWAIT0();
        __syncthreads();
        if (i < 35) load(i + 1);
        int s = i & 1;
        mma_chunk(sb + s * STAGEB, sb + s * STAGEB + TILEB, wn, wm, lane, acc);
    }

    float* dst = g_Y1;
    #pragma unroll
    for (int t = 0; t < 2; t++) {
        #pragma unroll
        for (int j = 0; j < 8; j++) {
            int nr = n0 + wn * 32 + t * 16 + (lane >> 2);
            int mc = m0 + wm * 64 + j * 8 + (lane & 3) * 2;
            float2 v0 = make_float2(acc[t][j][0], acc[t][j][1]);
            float2 v1 = make_float2(acc[t][j][2], acc[t][j][3]);
            *(float2*)&dst[(size_t)nr * 256 + mc]       = v0;
            *(float2*)&dst[(size_t)(nr + 8) * 256 + mc] = v1;
        }
    }
    #pragma unroll
    for (int j = 0; j < 8; j++) {
        float s0 = 0.f, q0 = 0.f, s1 = 0.f, q1 = 0.f;
        #pragma unroll
        for (int t = 0; t < 2; t++) {
            s0 += acc[t][j][0] + acc[t][j][2];
            q0 += acc[t][j][0] * acc[t][j][0] + acc[t][j][2] * acc[t][j][2];
            s1 += acc[t][j][1] + acc[t][j][3];
            q1 += acc[t][j][1] * acc[t][j][1] + acc[t][j][3] * acc[t][j][3];
        }
        #pragma unroll
        for (int off = 4; off < 32; off <<= 1) {
            s0 += __shfl_xor_sync(0xffffffffu, s0, off);
            q0 += __shfl_xor_sync(0xffffffffu, q0, off);
            s1 += __shfl_xor_sync(0xffffffffu, s1, off);
            q1 += __shfl_xor_sync(0xffffffffu, q1, off);
        }
        if (lane < 4) {
            int mc = m0 + wm * 64 + j * 8 + lane * 2;
            atomicAdd(&g_sum1[mc], s0);  atomicAdd(&g_sq1[mc], q0);
            atomicAdd(&g_sum1[mc + 1], s1); atomicAdd(&g_sq1[mc + 1], q1);
        }
    }
}

// ---------------- finalize BN ----------------
__global__ void finalize1_kernel(const float* __restrict__ g1, const float* __restrict__ be1) {
    int i = threadIdx.x;
    float mean = g_sum1[i] * (1.0f / NTOT);
    float var  = g_sq1[i] * (1.0f / NTOT) - mean * mean;
    float sc   = g1[i] * rsqrtf(var + EPS_BN);
    g_scale1[i] = sc;
    g_shift1[i] = be1[i] - mean * sc;
}
__global__ void finalize2_kernel(const float* __restrict__ g2, const float* __restrict__ be2) {
    int i = threadIdx.x;
    float mean = g_sum2[i] * (1.0f / NTOT);
    float var  = g_sq2[i] * (1.0f / NTOT) - mean * mean;
    float sc   = g2[i] * rsqrtf(var + EPS_BN);
    g_scale2[i] = sc;
    g_shift2[i] = be2[i] - mean * sc;
}

// ---------------- mid: X2 = hi/lo split of relu(BN1(Y1)) ----------------
__global__ void mid_kernel() {
    __shared__ float sc[M1], sh[M1];
    int tid = threadIdx.x;
    sc[tid] = g_scale1[tid]; sh[tid] = g_shift1[tid];
    __syncthreads();
    int i4 = blockIdx.x * 256 + tid;
    int n = i4 >> 6, c = (i4 & 63) * 4;
    float4 v = *(const float4*)&g_Y1[(size_t)n * 256 + c];
    float y0 = fmaxf(fmaf(sc[c + 0], v.x, sh[c + 0]), 0.f);
    float y1 = fmaxf(fmaf(sc[c + 1], v.y, sh[c + 1]), 0.f);
    float y2 = fmaxf(fmaf(sc[c + 2], v.z, sh[c + 2]), 0.f);
    float y3 = fmaxf(fmaf(sc[c + 3], v.w, sh[c + 3]), 0.f);
    __nv_bfloat16 h0 = bhi(y0), h1 = bhi(y1), h2 = bhi(y2), h3 = bhi(y3);
    size_t row = (size_t)n * X2ROW;
    __nv_bfloat162 o;
    o.x = h0; o.y = h1; *(__nv_bfloat162*)&g_X2[row + c] = o;
    o.x = h2; o.y = h3; *(__nv_bfloat162*)&g_X2[row + c + 2] = o;
    o.x = blo(y0, h0); o.y = blo(y1, h1); *(__nv_bfloat162*)&g_X2[row + 256 + c] = o;
    o.x = blo(y2, h2); o.y = blo(y3, h3); *(__nv_bfloat162*)&g_X2[row + 256 + c + 2] = o;
}

// ---------------- GEMM2: out = W2s @ X2 (HMMA), epilogue 2-pass transpose + BN2 ----------------
__global__ __launch_bounds__(256) void gemm2_tc(float* __restrict__ out) {
    extern __shared__ char dsm[];
    uint32_t sb = smem_u32(dsm);
    int tid = threadIdx.x, lane = tid & 31, wid = tid >> 5;
    int wn = wid & 3, wm = wid >> 2;
    int n0 = blockIdx.x * 128;

    const __nv_bfloat16* Xb = g_X2 + (size_t)n0 * X2ROW;
    const __nv_bfloat16* Wb = g_W2s;

    float acc[2][8][4];
    #pragma unroll
    for (int t = 0; t < 2; t++)
        #pragma unroll
        for (int j = 0; j < 8; j++)
            #pragma unroll
            for (int d = 0; d < 4; d++) acc[t][j][d] = 0.f;

    int row2 = tid >> 2, c4 = tid & 3;
    auto load = [&](int i) {
        int s = i & 1;
        int t = i / 8, kc = i % 8;
        int aoff = ((t == 1) ? 256 : 0) + kc * 32;
        int boff = ((t == 2) ? 256 : 0) + kc * 32;
        uint32_t dstA = sb + s * STAGEB;
        uint32_t dstB = dstA + TILEB;
        #pragma unroll
        for (int u = 0; u < 2; u++) {
            int r = row2 + u * 64;
            CP16(dstA + r * ROWB + c4 * 16, Xb + (size_t)r * X2ROW + aoff + c4 * 8);
            CP16(dstB + r * ROWB + c4 * 16, Wb + (size_t)r * W2ROW + boff + c4 * 8);
        }
        CPCOMMIT();
    };

    load(0);
    for (int i = 0; i < 24; i++) {
        CPWAIT0();
        __syncthreads();
        if (i < 23) load(i + 1);
        int s = i & 1;
        mma_chunk(sb + s * STAGEB, sb + s * STAGEB + TILEB, wn, wm, lane, acc);
    }

    // epilogue: two 64-channel passes through smem (fits in 40KB)
    float* smT = (float*)dsm;
    int b = n0 >> 14, nn = n0 & (N1 - 1);
    #pragma unroll
    for (int h = 0; h < 2; h++) {
        __syncthreads();
        if (wm == h) {
            #pragma unroll
            for (int t = 0; t < 2; t++)
                #pragma unroll
                for (int j = 0; j < 8; j++) {
                    int nr = wn * 32 + t * 16 + (lane >> 2);
                    int ml = j * 8 + (lane & 3) * 2;       // local channel within 64
                    smT[(ml)     * 136 + nr]     = acc[t][j][0];
                    smT[(ml + 1) * 136 + nr]     = acc[t][j][1];
                    smT[(ml)     * 136 + nr + 8] = acc[t][j][2];
                    smT[(ml + 1) * 136 + nr + 8] = acc[t][j][3];
                }
        }
        __syncthreads();
        for (int m = wid; m < 64; m += 8) {
            float4 v = *(float4*)&smT[m * 136 + lane * 4];
            *(float4*)&out[((size_t)b * M2 + h * 64 + m) * N1 + nn + lane * 4] = v;
        }
    }
    // BN2 stats
    #pragma unroll
    for (int j = 0; j < 8; j++) {
        float s0 = 0.f, q0 = 0.f, s1 = 0.f, q1 = 0.f;
        #pragma unroll
        for (int t = 0; t < 2; t++) {
            s0 += acc[t][j][0] + acc[t][j][2];
            q0 += acc[t][j][0] * acc[t][j][0] + acc[t][j][2] * acc[t][j][2];
            s1 += acc[t][j][1] + acc[t][j][3];
            q1 += acc[t][j][1] * acc[t][j][1] + acc[t][j][3] * acc[t][j][3];
        }
        #pragma unroll
        for (int off = 4; off < 32; off <<= 1) {
            s0 += __shfl_xor_sync(0xffffffffu, s0, off);
            q0 += __shfl_xor_sync(0xffffffffu, q0, off);
            s1 += __shfl_xor_sync(0xffffffffu, s1, off);
            q1 += __shfl_xor_sync(0xffffffffu, q1, off);
        }
        if (lane < 4) {
            int mc = wm * 64 + j * 8 + lane * 2;
            atomicAdd(&g_sum2[mc], s0);  atomicAdd(&g_sq2[mc], q0);
            atomicAdd(&g_sum2[mc + 1], s1); atomicAdd(&g_sq2[mc + 1], q1);
        }
    }
}

// ---------------- final BN2 + relu in place ----------------
__global__ void bn2_kernel(float* __restrict__ out) {
    int i4 = blockIdx.x * 256 + threadIdx.x;
    int m  = (i4 >> 12) & 127;
    float s = g_scale2[m], t = g_shift2[m];
    float4 v = ((float4*)out)[i4];
    v.x = fmaxf(fmaf(s, v.x, t), 0.f);
    v.y = fmaxf(fmaf(s, v.y, t), 0.f);
    v.z = fmaxf(fmaf(s, v.z, t), 0.f);
    v.w = fmaxf(fmaf(s, v.w, t), 0.f);
    ((float4*)out)[i4] = v;
}

// ---------------- launcher ----------------
extern "C" void kernel_launch(void* const* d_in, const int* in_sizes, int n_in,
                              void* d_out, int out_size) {
    const float* xyz1    = (const float*)d_in[0];
    const float* xyz2    = (const float*)d_in[1];
    const float* points1 = (const float*)d_in[2];
    const float* points2 = (const float*)d_in[3];
    const float* W1      = (const float*)d_in[4];
    const float* g1      = (const float*)d_in[6];
    const float* be1     = (const float*)d_in[7];
    const float* W2      = (const float*)d_in[8];
    const float* g2      = (const float*)d_in[10];
    const float* be2     = (const float*)d_in[11];
    float* out = (float*)d_out;

    cudaFuncSetAttribute(gemm1_tc, cudaFuncAttributeMaxDynamicSharedMemorySize, SMEM_DYN);
    cudaFuncSetAttribute(gemm2_tc, cudaFuncAttributeMaxDynamicSharedMemorySize, SMEM_DYN);

    init_kernel<<<1, 256>>>();
    sort_kernel<<<BB, 1024>>>(xyz2);
    transpose_p2_kernel<<<dim3(N2 / 32, C2 / 32, BB), dim3(32, 8)>>>(points2);
    cvt_w_kernel<<<(M1 * 384) / 256, 256>>>(W1, W2);
    knn_pruned_kernel<<<dim3(N1 / 256, BB), 256>>>(xyz1);
    cvt_p1_kernel<<<dim3(N1 / 32, C1 / 32, BB), 256>>>(points1);
    interp_kernel<<<NTOT / 8, 256>>>();
    gemm1_tc<<<dim3(NTOT / 128, 2), 256, SMEM_DYN>>>();
    finalize1_kernel<<<1, M1>>>(g1, be1);
    mid_kernel<<<(NTOT * 64) / 256, 256>>>();
    gemm2_tc<<<dim3(NTOT / 128, 1), 256, SMEM_DYN>>>(out);
    finalize2_kernel<<<1, M2>>>(g2, be2);
    bn2_kernel<<<(NTOT * M2 / 4) / 256, 256>>>(out);
}

// round 11
// speedup vs baseline: 1.4712x; 1.4712x over previous
#include <cuda_runtime.h>
#include <cuda_bf16.h>
#include <cstdint>

#define BB   4
#define N1   16384
#define N2   4096
#define C1   128
#define C2   256
#define M1   256
#define M2   128
#define NTOT 65536
#define EPS_BN 1e-5f

// K-stacked bf16 operand layouts (hi | lo)
#define X1ROW 768
#define W1ROW 768
#define X2ROW 512
#define W2ROW 512

// ---------------- scratch (static device globals) ----------------
__device__ __nv_bfloat16 g_X1[(size_t)NTOT * X1ROW];
__device__ __nv_bfloat16 g_X2[(size_t)NTOT * X2ROW];
__device__ __nv_bfloat16 g_W1s[M1 * W1ROW];
__device__ __nv_bfloat16 g_W2s[M2 * W2ROW];
__device__ float g_Y1[(size_t)NTOT * M1];
__device__ float g_p2t[BB * N2 * C2];
__device__ float g_pd[12 * NTOT];                     // per-quarter top3 r-vals
__device__ int   g_pi[12 * NTOT];
__device__ int   g_i0[NTOT], g_i1[NTOT], g_i2[NTOT];
__device__ float g_w0[NTOT], g_w1[NTOT], g_w2[NTOT];
__device__ float g_sum1[M1], g_sq1[M1], g_scale1[M1], g_shift1[M1];
__device__ float g_sum2[M2], g_sq2[M2], g_scale2[M2], g_shift2[M2];

// ---------------- helpers ----------------
__device__ __forceinline__ uint32_t smem_u32(const void* p) {
    uint32_t a;
    asm("{ .reg .u64 t; cvta.to.shared.u64 t, %1; cvt.u32.u64 %0, t; }" : "=r"(a) : "l"(p));
    return a;
}
#define CP16(dst, src) \
    asm volatile("cp.async.cg.shared.global [%0], [%1], 16;" :: "r"(dst), "l"(src) : "memory")
#define CPCOMMIT() asm volatile("cp.async.commit_group;" ::: "memory")
#define CPWAIT0()  asm volatile("cp.async.wait_group 0;" ::: "memory")

#define LDM4(r, addr) \
    asm volatile("ldmatrix.sync.aligned.m8n8.x4.shared.b16 {%0,%1,%2,%3}, [%4];" \
        : "=r"((r)[0]), "=r"((r)[1]), "=r"((r)[2]), "=r"((r)[3]) : "r"(addr))

#define MMA(d, a, b0, b1) \
    asm volatile("mma.sync.aligned.m16n8k16.row.col.f32.bf16.bf16.f32 " \
        "{%0,%1,%2,%3},{%4,%5,%6,%7},{%8,%9},{%0,%1,%2,%3};" \
        : "+f"((d)[0]), "+f"((d)[1]), "+f"((d)[2]), "+f"((d)[3]) \
        : "r"((a)[0]), "r"((a)[1]), "r"((a)[2]), "r"((a)[3]), "r"(b0), "r"(b1))

__device__ __forceinline__ __nv_bfloat16 bhi(float x) { return __float2bfloat16(x); }
__device__ __forceinline__ __nv_bfloat16 blo(float x, __nv_bfloat16 h) {
    return __float2bfloat16(x - __bfloat162float(h));
}

#define ROWB   80
#define TILEB  10240
#define STAGEB 20480
#define SMEM_DYN 40960   // 2 mainloop stages; gemm2 epilogue 64x136x4=34816

// ---------------- init ----------------
__global__ void init_kernel() {
    int t = threadIdx.x;
    if (t < M1) { g_sum1[t] = 0.f; g_sq1[t] = 0.f; }
    if (t < M2) { g_sum2[t] = 0.f; g_sq2[t] = 0.f; }
}

// ---------------- transpose points2 (B,C2,N2) -> (B,N2,C2) ----------------
__global__ void transpose_p2_kernel(const float* __restrict__ p2) {
    __shared__ float tile[32][33];
    int b = blockIdx.z, n0 = blockIdx.x * 32, c0 = blockIdx.y * 32;
    const float* src = p2 + (size_t)b * C2 * N2;
    #pragma unroll
    for (int i = 0; i < 32; i += 8)
        tile[threadIdx.y + i][threadIdx.x] = src[(size_t)(c0 + threadIdx.y + i) * N2 + n0 + threadIdx.x];
    __syncthreads();
    float* dst = g_p2t + (size_t)b * N2 * C2;
    #pragma unroll
    for (int i = 0; i < 32; i += 8)
        dst[(size_t)(n0 + threadIdx.y + i) * C2 + c0 + threadIdx.x] = tile[threadIdx.x][threadIdx.y + i];
}

// ---------------- W hi/lo prep ----------------
__global__ void cvt_w_kernel(const float* __restrict__ W1, const float* __restrict__ W2) {
    int i = blockIdx.x * 256 + threadIdx.x;
    if (i < M1 * 384) {
        int r = i / 384, c = i % 384;
        float w = W1[i];
        __nv_bfloat16 h = bhi(w);
        g_W1s[r * W1ROW + c] = h;
        g_W1s[r * W1ROW + 384 + c] = blo(w, h);
    }
    if (i < M2 * 256) {
        int r = i / 256, c = i % 256;
        float w = W2[i];
        __nv_bfloat16 h = bhi(w);
        g_W2s[r * W2ROW + c] = h;
        g_W2s[r * W2ROW + 256 + c] = blo(w, h);
    }
}

// ---------------- points1 -> X1 cols[0..127]=hi, [384..511]=lo ----------------
__global__ void cvt_p1_kernel(const float* __restrict__ points1) {
    __shared__ float tile[32][33];
    int b = blockIdx.z, n0 = blockIdx.x * 32, c0 = blockIdx.y * 32;
    int tx = threadIdx.x & 31, ty = threadIdx.x >> 5;
    const float* src = points1 + (size_t)b * C1 * N1;
    #pragma unroll
    for (int i = 0; i < 32; i += 8)
        tile[ty + i][tx] = src[(size_t)(c0 + ty + i) * N1 + n0 + tx];
    __syncthreads();
    int p = threadIdx.x >> 3, g = threadIdx.x & 7;
    float f0 = tile[g * 4 + 0][p], f1 = tile[g * 4 + 1][p];
    float f2 = tile[g * 4 + 2][p], f3 = tile[g * 4 + 3][p];
    __nv_bfloat16 h0 = bhi(f0), h1 = bhi(f1), h2 = bhi(f2), h3 = bhi(f3);
    size_t row = (size_t)(b * N1 + n0 + p) * X1ROW;
    __nv_bfloat162 v;
    v.x = h0; v.y = h1; *(__nv_bfloat162*)&g_X1[row + c0 + g * 4] = v;
    v.x = h2; v.y = h3; *(__nv_bfloat162*)&g_X1[row + c0 + g * 4 + 2] = v;
    v.x = blo(f0, h0); v.y = blo(f1, h1); *(__nv_bfloat162*)&g_X1[row + 384 + c0 + g * 4] = v;
    v.x = blo(f2, h2); v.y = blo(f3, h3); *(__nv_bfloat162*)&g_X1[row + 384 + c0 + g * 4 + 2] = v;
}

// ---------------- 3-NN pass 1: quartered scan, branch-free insert ----------------
__global__ void knn_kernel(const float* __restrict__ xyz1, const float* __restrict__ xyz2) {
    __shared__ float4 sh[1024];           // 16 KB
    int b    = blockIdx.z;
    int half = blockIdx.y;                // quarter 0..3
    int n    = blockIdx.x * 256 + threadIdx.x;
    int base = half * 1024;
    const float* x1 = xyz1 + (size_t)b * 3 * N1;
    const float* x2 = xyz2 + (size_t)b * 3 * N2;
    for (int t = threadIdx.x; t < 1024; t += 256) {
        float px = x2[base + t], py = x2[N2 + base + t], pz = x2[2 * N2 + base + t];
        sh[t] = make_float4(px, py, pz, px * px + py * py + pz * pz);
    }
    float qx = x1[n], qy = x1[N1 + n], qz = x1[2 * N1 + n];
    float m2x = -2.0f * qx, m2y = -2.0f * qy, m2z = -2.0f * qz;
    float d0 = 3.4e38f, d1 = 3.4e38f, d2 = 3.4e38f;
    int   i0 = 0, i1 = 0, i2 = 0;
    __syncthreads();
    #pragma unroll 8
    for (int j = 0; j < 1024; j++) {
        float4 p = sh[j];
        float r = fmaf(m2x, p.x, fmaf(m2y, p.y, fmaf(m2z, p.z, p.w)));
        if (r < d2) {                          // single outer guard
            bool b1 = r < d1, b0 = r < d0;
            int jg = base + j;
            d2 = b1 ? d1 : r;  i2 = b1 ? i1 : jg;
            d1 = b1 ? (b0 ? d0 : r) : d1;
            i1 = b1 ? (b0 ? i0 : jg) : i1;
            d0 = b0 ? r : d0;  i0 = b0 ? jg : i0;
        }
    }
    int p = b * N1 + n;
    g_pd[(half * 3 + 0) * NTOT + p] = d0; g_pi[(half * 3 + 0) * NTOT + p] = i0;
    g_pd[(half * 3 + 1) * NTOT + p] = d1; g_pi[(half * 3 + 1) * NTOT + p] = i1;
    g_pd[(half * 3 + 2) * NTOT + p] = d2; g_pi[(half * 3 + 2) * NTOT + p] = i2;
}

// ---------------- 3-NN pass 2: merge 4 quarters, exact dists -> weights ----------------
__global__ void knn_merge_kernel(const float* __restrict__ xyz1, const float* __restrict__ xyz2) {
    int p = blockIdx.x * 256 + threadIdx.x;
    int b = p >> 14, n = p & (N1 - 1);
    float d0 = 3.4e38f, d1 = 3.4e38f, d2 = 3.4e38f;
    int   i0 = 0, i1 = 0, i2 = 0;
    #pragma unroll
    for (int e = 0; e < 12; e++) {        // quarters in order; entries sorted within
        float r = g_pd[e * NTOT + p];
        int  jg = g_pi[e * NTOT + p];
        if (r < d2) {
            bool b1 = r < d1, b0 = r < d0;
            d2 = b1 ? d1 : r;  i2 = b1 ? i1 : jg;
            d1 = b1 ? (b0 ? d0 : r) : d1;
            i1 = b1 ? (b0 ? i0 : jg) : i1;
            d0 = b0 ? r : d0;  i0 = b0 ? jg : i0;
        }
    }
    const float* x1 = xyz1 + (size_t)b * 3 * N1;
    const float* x2 = xyz2 + (size_t)b * 3 * N2;
    float qx = x1[n], qy = x1[N1 + n], qz = x1[2 * N1 + n];
    int   id[3] = { i0, i1, i2 };
    float w[3];
    #pragma unroll
    for (int t = 0; t < 3; t++) {
        float px = x2[id[t]], py = x2[N2 + id[t]], pz = x2[2 * N2 + id[t]];
        float dx = qx - px, dy = qy - py, dz = qz - pz;
        float dd = fmaxf(dx * dx + dy * dy + dz * dz, 1e-10f);
        w[t] = 1.0f / dd;
    }
    float ws = w[0] + w[1] + w[2];
    g_i0[p] = i0; g_i1[p] = i1; g_i2[p] = i2;
    g_w0[p] = w[0] / ws; g_w1[p] = w[1] / ws; g_w2[p] = w[2] / ws;
}

// ---------------- interp -> X1 cols[128..383]=hi, [512..767]=lo ----------------
__global__ void interp_kernel() {
    int p    = blockIdx.x * 8 + (threadIdx.x >> 5);
    int lane = threadIdx.x & 31;
    int b    = p >> 14;
    float w0 = g_w0[p], w1 = g_w1[p], w2 = g_w2[p];
    const float4* r0 = (const float4*)(g_p2t + ((size_t)b * N2 + g_i0[p]) * C2);
    const float4* r1 = (const float4*)(g_p2t + ((size_t)b * N2 + g_i1[p]) * C2);
    const float4* r2 = (const float4*)(g_p2t + ((size_t)b * N2 + g_i2[p]) * C2);
    size_t row = (size_t)p * X1ROW;
    int cA = lane, cB = lane + 32;
    float4 a0 = r0[cA], e0 = r1[cA], f0 = r2[cA];
    float4 a1 = r0[cB], e1 = r1[cB], f1 = r2[cB];
    #pragma unroll
    for (int it = 0; it < 2; it++) {
        float4 a = it ? a1 : a0, e = it ? e1 : e0, f = it ? f1 : f0;
        int c = it ? cB : cA;
        float ox = w0 * a.x + w1 * e.x + w2 * f.x;
        float oy = w0 * a.y + w1 * e.y + w2 * f.y;
        float oz = w0 * a.z + w1 * e.z + w2 * f.z;
        float ow = w0 * a.w + w1 * e.w + w2 * f.w;
        __nv_bfloat16 h0 = bhi(ox), h1 = bhi(oy), h2 = bhi(oz), h3 = bhi(ow);
        __nv_bfloat162 v;
        v.x = h0; v.y = h1; *(__nv_bfloat162*)&g_X1[row + 128 + 4 * c] = v;
        v.x = h2; v.y = h3; *(__nv_bfloat162*)&g_X1[row + 128 + 4 * c + 2] = v;
        v.x = blo(ox, h0); v.y = blo(oy, h1); *(__nv_bfloat162*)&g_X1[row + 512 + 4 * c] = v;
        v.x = blo(oz, h2); v.y = blo(ow, h3); *(__nv_bfloat162*)&g_X1[row + 512 + 4 * c + 2] = v;
    }
}

// ---------------- shared mainloop piece: one BK=32 chunk of HMMA ----------------
__device__ __forceinline__ void mma_chunk(uint32_t smA, uint32_t smB, int wn, int wm,
                                          int lane, float acc[2][8][4]) {
    uint32_t rsel = (uint32_t)(lane & 15);
    uint32_t csel = (uint32_t)(lane >> 4) * 16;
    #pragma unroll
    for (int ks = 0; ks < 2; ks++) {
        uint32_t af[2][4], bf[4][4];
        #pragma unroll
        for (int t = 0; t < 2; t++)
            LDM4(af[t], smA + (wn * 32 + t * 16 + rsel) * ROWB + ks * 32 + csel);
        #pragma unroll
        for (int jj = 0; jj < 4; jj++)
            LDM4(bf[jj], smB + (wm * 64 + jj * 16 + rsel) * ROWB + ks * 32 + csel);
        #pragma unroll
        for (int t = 0; t < 2; t++)
            #pragma unroll
            for (int j = 0; j < 8; j++)
                MMA(acc[t][j], af[t], bf[j >> 1][(j & 1)], bf[j >> 1][(j & 1) + 2]);
    }
}

// ---------------- GEMM1: Y1[n][m] = sum_k X1[n,k]*W1s[m,k]; m on blockIdx.x for L2 reuse ----------------
__global__ __launch_bounds__(256) void gemm1_tc() {
    extern __shared__ char dsm[];
    uint32_t sb = smem_u32(dsm);
    int tid = threadIdx.x, lane = tid & 31, wid = tid >> 5;
    int wn = wid & 3, wm = wid >> 2;
    int m0 = blockIdx.x * 128, n0 = blockIdx.y * 128;   // x fastest -> m-pair shares n-tile in L2

    const __nv_bfloat16* Xb = g_X1  + (size_t)n0 * X1ROW;
    const __nv_bfloat16* Wb = g_W1s + (size_t)m0 * W1ROW;

    float acc[2][8][4];
    #pragma unroll
    for (int t = 0; t < 2; t++)
        #pragma unroll
        for (int j = 0; j < 8; j++)
            #pragma unroll
            for (int d = 0; d < 4; d++) acc[t][j][d] = 0.f;

    int row2 = tid >> 2, c4 = tid & 3;
    auto load = [&](int i) {
        int s = i & 1;
        int t = i / 12, kc = i % 12;
        int aoff = ((t == 1) ? 384 : 0) + kc * 32;
        int boff = ((t == 2) ? 384 : 0) + kc * 32;
        uint32_t dstA = sb + s * STAGEB;
        uint32_t dstB = dstA + TILEB;
        #pragma unroll
        for (int u = 0; u < 2; u++) {
            int r = row2 + u * 64;
            CP16(dstA + r * ROWB + c4 * 16, Xb + (size_t)r * X1ROW + aoff + c4 * 8);
            CP16(dstB + r * ROWB + c4 * 16, Wb + (size_t)r * W1ROW + boff + c4 * 8);
        }
        CPCOMMIT();
    };

    load(0);
    for (int i = 0; i < 36; i++) {
        CPWAIT0();
        __syncthreads();
        if (i < 35) load(i + 1);
        int s = i & 1;
        mma_chunk(sb + s * STAGEB, sb + s * STAGEB + TILEB, wn, wm, lane, acc);
    }

    float* dst = g_Y1;
    #pragma unroll
    for (int t = 0; t < 2; t++) {
        #pragma unroll
        for (int j = 0; j < 8; j++) {
            int nr = n0 + wn * 32 + t * 16 + (lane >> 2);
            int mc = m0 + wm * 64 + j * 8 + (lane & 3) * 2;
            float2 v0 = make_float2(acc[t][j][0], acc[t][j][1]);
            float2 v1 = make_float2(acc[t][j][2], acc[t][j][3]);
            *(float2*)&dst[(size_t)nr * 256 + mc]       = v0;
            *(float2*)&dst[(size_t)(nr + 8) * 256 + mc] = v1;
        }
    }
    #pragma unroll
    for (int j = 0; j < 8; j++) {
        float s0 = 0.f, q0 = 0.f, s1 = 0.f, q1 = 0.f;
        #pragma unroll
        for (int t = 0; t < 2; t++) {
            s0 += acc[t][j][0] + acc[t][j][2];
            q0 += acc[t][j][0] * acc[t][j][0] + acc[t][j][2] * acc[t][j][2];
            s1 += acc[t][j][1] + acc[t][j][3];
            q1 += acc[t][j][1] * acc[t][j][1] + acc[t][j][3] * acc[t][j][3];
        }
        #pragma unroll
        for (int off = 4; off < 32; off <<= 1) {
            s0 += __shfl_xor_sync(0xffffffffu, s0, off);
            q0 += __shfl_xor_sync(0xffffffffu, q0, off);
            s1 += __shfl_xor_sync(0xffffffffu, s1, off);
            q1 += __shfl_xor_sync(0xffffffffu, q1, off);
        }
        if (lane < 4) {
            int mc = m0 + wm * 64 + j * 8 + lane * 2;
            atomicAdd(&g_sum1[mc], s0);  atomicAdd(&g_sq1[mc], q0);
            atomicAdd(&g_sum1[mc + 1], s1); atomicAdd(&g_sq1[mc + 1], q1);
        }
    }
}

// ---------------- finalize BN ----------------
__global__ void finalize1_kernel(const float* __restrict__ g1, const float* __restrict__ be1) {
    int i = threadIdx.x;
    float mean = g_sum1[i] * (1.0f / NTOT);
    float var  = g_sq1[i] * (1.0f / NTOT) - mean * mean;
    float sc   = g1[i] * rsqrtf(var + EPS_BN);
    g_scale1[i] = sc;
    g_shift1[i] = be1[i] - mean * sc;
}
__global__ void finalize2_kernel(const float* __restrict__ g2, const float* __restrict__ be2) {
    int i = threadIdx.x;
    float mean = g_sum2[i] * (1.0f / NTOT);
    float var  = g_sq2[i] * (1.0f / NTOT) - mean * mean;
    float sc   = g2[i] * rsqrtf(var + EPS_BN);
    g_scale2[i] = sc;
    g_shift2[i] = be2[i] - mean * sc;
}

// ---------------- mid: X2 = hi/lo split of relu(BN1(Y1)) ----------------
__global__ void mid_kernel() {
    __shared__ float sc[M1], sh[M1];
    int tid = threadIdx.x;
    sc[tid] = g_scale1[tid]; sh[tid] = g_shift1[tid];
    __syncthreads();
    int i4 = blockIdx.x * 256 + tid;
    int n = i4 >> 6, c = (i4 & 63) * 4;
    float4 v = *(const float4*)&g_Y1[(size_t)n * 256 + c];
    float y0 = fmaxf(fmaf(sc[c + 0], v.x, sh[c + 0]), 0.f);
    float y1 = fmaxf(fmaf(sc[c + 1], v.y, sh[c + 1]), 0.f);
    float y2 = fmaxf(fmaf(sc[c + 2], v.z, sh[c + 2]), 0.f);
    float y3 = fmaxf(fmaf(sc[c + 3], v.w, sh[c + 3]), 0.f);
    __nv_bfloat16 h0 = bhi(y0), h1 = bhi(y1), h2 = bhi(y2), h3 = bhi(y3);
    size_t row = (size_t)n * X2ROW;
    __nv_bfloat162 o;
    o.x = h0; o.y = h1; *(__nv_bfloat162*)&g_X2[row + c] = o;
    o.x = h2; o.y = h3; *(__nv_bfloat162*)&g_X2[row + c + 2] = o;
    o.x = blo(y0, h0); o.y = blo(y1, h1); *(__nv_bfloat162*)&g_X2[row + 256 + c] = o;
    o.x = blo(y2, h2); o.y = blo(y3, h3); *(__nv_bfloat162*)&g_X2[row + 256 + c + 2] = o;
}

// ---------------- GEMM2: out = W2s @ X2 (HMMA), epilogue 2-pass transpose + BN2 ----------------
__global__ __launch_bounds__(256) void gemm2_tc(float* __restrict__ out) {
    extern __shared__ char dsm[];
    uint32_t sb = smem_u32(dsm);
    int tid = threadIdx.x, lane = tid & 31, wid = tid >> 5;
    int wn = wid & 3, wm = wid >> 2;
    int n0 = blockIdx.x * 128;

    const __nv_bfloat16* Xb = g_X2 + (size_t)n0 * X2ROW;
    const __nv_bfloat16* Wb = g_W2s;

    float acc[2][8][4];
    #pragma unroll
    for (int t = 0; t < 2; t++)
        #pragma unroll
        for (int j = 0; j < 8; j++)
            #pragma unroll
            for (int d = 0; d < 4; d++) acc[t][j][d] = 0.f;

    int row2 = tid >> 2, c4 = tid & 3;
    auto load = [&](int i) {
        int s = i & 1;
        int t = i / 8, kc = i % 8;
        int aoff = ((t == 1) ? 256 : 0) + kc * 32;
        int boff = ((t == 2) ? 256 : 0) + kc * 32;
        uint32_t dstA = sb + s * STAGEB;
        uint32_t dstB = dstA + TILEB;
        #pragma unroll
        for (int u = 0; u < 2; u++) {
            int r = row2 + u * 64;
            CP16(dstA + r * ROWB + c4 * 16, Xb + (size_t)r * X2ROW + aoff + c4 * 8);
            CP16(dstB + r * ROWB + c4 * 16, Wb + (size_t)r * W2ROW + boff + c4 * 8);
        }
        CPCOMMIT();
    };

    load(0);
    for (int i = 0; i < 24; i++) {
        CPWAIT0();
        __syncthreads();
        if (i < 23) load(i + 1);
        int s = i & 1;
        mma_chunk(sb + s * STAGEB, sb + s * STAGEB + TILEB, wn, wm, lane, acc);
    }

    // epilogue: two 64-channel passes through smem
    float* smT = (float*)dsm;
    int b = n0 >> 14, nn = n0 & (N1 - 1);
    #pragma unroll
    for (int h = 0; h < 2; h++) {
        __syncthreads();
        if (wm == h) {
            #pragma unroll
            for (int t = 0; t < 2; t++)
                #pragma unroll
                for (int j = 0; j < 8; j++) {
                    int nr = wn * 32 + t * 16 + (lane >> 2);
                    int ml = j * 8 + (lane & 3) * 2;
                    smT[(ml)     * 136 + nr]     = acc[t][j][0];
                    smT[(ml + 1) * 136 + nr]     = acc[t][j][1];
                    smT[(ml)     * 136 + nr + 8] = acc[t][j][2];
                    smT[(ml + 1) * 136 + nr + 8] = acc[t][j][3];
                }
        }
        __syncthreads();
        for (int m = wid; m < 64; m += 8) {
            float4 v = *(float4*)&smT[m * 136 + lane * 4];
            *(float4*)&out[((size_t)b * M2 + h * 64 + m) * N1 + nn + lane * 4] = v;
        }
    }
    // BN2 stats
    #pragma unroll
    for (int j = 0; j < 8; j++) {
        float s0 = 0.f, q0 = 0.f, s1 = 0.f, q1 = 0.f;
        #pragma unroll
        for (int t = 0; t < 2; t++) {
            s0 += acc[t][j][0] + acc[t][j][2];
            q0 += acc[t][j][0] * acc[t][j][0] + acc[t][j][2] * acc[t][j][2];
            s1 += acc[t][j][1] + acc[t][j][3];
            q1 += acc[t][j][1] * acc[t][j][1] + acc[t][j][3] * acc[t][j][3];
        }
        #pragma unroll
        for (int off = 4; off < 32; off <<= 1) {
            s0 += __shfl_xor_sync(0xffffffffu, s0, off);
            q0 += __shfl_xor_sync(0xffffffffu, q0, off);
            s1 += __shfl_xor_sync(0xffffffffu, s1, off);
            q1 += __shfl_xor_sync(0xffffffffu, q1, off);
        }
        if (lane < 4) {
            int mc = wm * 64 + j * 8 + lane * 2;
            atomicAdd(&g_sum2[mc], s0);  atomicAdd(&g_sq2[mc], q0);
            atomicAdd(&g_sum2[mc + 1], s1); atomicAdd(&g_sq2[mc + 1], q1);
        }
    }
}

// ---------------- final BN2 + relu in place ----------------
__global__ void bn2_kernel(float* __restrict__ out) {
    int i4 = blockIdx.x * 256 + threadIdx.x;
    int m  = (i4 >> 12) & 127;
    float s = g_scale2[m], t = g_shift2[m];
    float4 v = ((float4*)out)[i4];
    v.x = fmaxf(fmaf(s, v.x, t), 0.f);
    v.y = fmaxf(fmaf(s, v.y, t), 0.f);
    v.z = fmaxf(fmaf(s, v.z, t), 0.f);
    v.w = fmaxf(fmaf(s, v.w, t), 0.f);
    ((float4*)out)[i4] = v;
}

// ---------------- launcher ----------------
extern "C" void kernel_launch(void* const* d_in, const int* in_sizes, int n_in,
                              void* d_out, int out_size) {
    const float* xyz1    = (const float*)d_in[0];
    const float* xyz2    = (const float*)d_in[1];
    const float* points1 = (const float*)d_in[2];
    const float* points2 = (const float*)d_in[3];
    const float* W1      = (const float*)d_in[4];
    const float* g1      = (const float*)d_in[6];
    const float* be1     = (const float*)d_in[7];
    const float* W2      = (const float*)d_in[8];
    const float* g2      = (const float*)d_in[10];
    const float* be2     = (const float*)d_in[11];
    float* out = (float*)d_out;

    cudaFuncSetAttribute(gemm1_tc, cudaFuncAttributeMaxDynamicSharedMemorySize, SMEM_DYN);
    cudaFuncSetAttribute(gemm2_tc, cudaFuncAttributeMaxDynamicSharedMemorySize, SMEM_DYN);

    init_kernel<<<1, 256>>>();
    transpose_p2_kernel<<<dim3(N2 / 32, C2 / 32, BB), dim3(32, 8)>>>(points2);
    cvt_w_kernel<<<(M1 * 384) / 256, 256>>>(W1, W2);
    knn_kernel<<<dim3(N1 / 256, 4, BB), 256>>>(xyz1, xyz2);
    knn_merge_kernel<<<NTOT / 256, 256>>>(xyz1, xyz2);
    cvt_p1_kernel<<<dim3(N1 / 32, C1 / 32, BB), 256>>>(points1);
    interp_kernel<<<NTOT / 8, 256>>>();
    gemm1_tc<<<dim3(2, NTOT / 128), 256, SMEM_DYN>>>();
    finalize1_kernel<<<1, M1>>>(g1, be1);
    mid_kernel<<<(NTOT * 64) / 256, 256>>>();
    gemm2_tc<<<dim3(NTOT / 128, 1), 256, SMEM_DYN>>>(out);
    finalize2_kernel<<<1, M2>>>(g2, be2);
    bn2_kernel<<<(NTOT * M2 / 4) / 256, 256>>>(out);
}

// round 12
// speedup vs baseline: 1.4780x; 1.0046x over previous
#include <cuda_runtime.h>
#include <cuda_bf16.h>
#include <cstdint>

#define BB   4
#define N1   16384
#define N2   4096
#define C1   128
#define C2   256
#define M1   256
#define M2   128
#define NTOT 65536
#define EPS_BN 1e-5f

// K-stacked bf16 operand layouts (hi | lo)
#define X1ROW 768
#define W1ROW 768
#define X2ROW 512
#define W2ROW 512

// ---------------- scratch (static device globals) ----------------
__device__ __nv_bfloat16 g_X1[(size_t)NTOT * X1ROW];
__device__ __nv_bfloat16 g_X2[(size_t)NTOT * X2ROW];
__device__ __nv_bfloat16 g_W1s[M1 * W1ROW];
__device__ __nv_bfloat16 g_W2s[M2 * W2ROW];
__device__ float g_Y1[(size_t)NTOT * M1];
__device__ float g_p2t[BB * N2 * C2];
__device__ float g_pd[12 * NTOT];                     // per-quarter top3 r-vals
__device__ int   g_pi[12 * NTOT];
__device__ int   g_i0[NTOT], g_i1[NTOT], g_i2[NTOT];
__device__ float g_w0[NTOT], g_w1[NTOT], g_w2[NTOT];
__device__ float g_sum1[M1], g_sq1[M1], g_scale1[M1], g_shift1[M1];
__device__ float g_sum2[M2], g_sq2[M2], g_scale2[M2], g_shift2[M2];

// ---------------- helpers ----------------
__device__ __forceinline__ uint32_t smem_u32(const void* p) {
    uint32_t a;
    asm("{ .reg .u64 t; cvta.to.shared.u64 t, %1; cvt.u32.u64 %0, t; }" : "=r"(a) : "l"(p));
    return a;
}
#define CP16(dst, src) \
    asm volatile("cp.async.cg.shared.global [%0], [%1], 16;" :: "r"(dst), "l"(src) : "memory")
#define CPCOMMIT() asm volatile("cp.async.commit_group;" ::: "memory")
#define CPWAIT0()  asm volatile("cp.async.wait_group 0;" ::: "memory")
#define CPWAIT1()  asm volatile("cp.async.wait_group 1;" ::: "memory")

#define LDM4(r, addr) \
    asm volatile("ldmatrix.sync.aligned.m8n8.x4.shared.b16 {%0,%1,%2,%3}, [%4];" \
        : "=r"((r)[0]), "=r"((r)[1]), "=r"((r)[2]), "=r"((r)[3]) : "r"(addr))

#define MMA(d, a, b0, b1) \
    asm volatile("mma.sync.aligned.m16n8k16.row.col.f32.bf16.bf16.f32 " \
        "{%0,%1,%2,%3},{%4,%5,%6,%7},{%8,%9},{%0,%1,%2,%3};" \
        : "+f"((d)[0]), "+f"((d)[1]), "+f"((d)[2]), "+f"((d)[3]) \
        : "r"((a)[0]), "r"((a)[1]), "r"((a)[2]), "r"((a)[3]), "r"(b0), "r"(b1))

__device__ __forceinline__ __nv_bfloat16 bhi(float x) { return __float2bfloat16(x); }
__device__ __forceinline__ __nv_bfloat16 blo(float x, __nv_bfloat16 h) {
    return __float2bfloat16(x - __bfloat162float(h));
}

// f32x2 packed-FMA helpers (Blackwell)
__device__ __forceinline__ unsigned long long pk2(float lo, float hi) {
    unsigned long long r;
    asm("mov.b64 %0, {%1, %2};" : "=l"(r) : "f"(lo), "f"(hi));
    return r;
}
__device__ __forceinline__ unsigned long long dup2(float x) {
    unsigned long long r;
    asm("mov.b64 %0, {%1, %1};" : "=l"(r) : "f"(x));
    return r;
}
__device__ __forceinline__ void fma2(unsigned long long& d, unsigned long long a, unsigned long long b) {
    asm("fma.rn.f32x2 %0, %1, %2, %0;" : "+l"(d) : "l"(a), "l"(b));
}
__device__ __forceinline__ float2 up2(unsigned long long v) {
    float2 f;
    asm("mov.b64 {%0, %1}, %2;" : "=f"(f.x), "=f"(f.y) : "l"(v));
    return f;
}

#define ROWB   80
#define TILEB  10240
#define STAGEB 20480
#define SMEM_DYN 61440   // 3 mainloop stages; gemm2 epilogue 64x136x4=34816 fits

// ---------------- init ----------------
__global__ void init_kernel() {
    int t = threadIdx.x;
    if (t < M1) { g_sum1[t] = 0.f; g_sq1[t] = 0.f; }
    if (t < M2) { g_sum2[t] = 0.f; g_sq2[t] = 0.f; }
}

// ---------------- transpose points2 (B,C2,N2) -> (B,N2,C2) ----------------
__global__ void transpose_p2_kernel(const float* __restrict__ p2) {
    __shared__ float tile[32][33];
    int b = blockIdx.z, n0 = blockIdx.x * 32, c0 = blockIdx.y * 32;
    const float* src = p2 + (size_t)b * C2 * N2;
    #pragma unroll
    for (int i = 0; i < 32; i += 8)
        tile[threadIdx.y + i][threadIdx.x] = src[(size_t)(c0 + threadIdx.y + i) * N2 + n0 + threadIdx.x];
    __syncthreads();
    float* dst = g_p2t + (size_t)b * N2 * C2;
    #pragma unroll
    for (int i = 0; i < 32; i += 8)
        dst[(size_t)(n0 + threadIdx.y + i) * C2 + c0 + threadIdx.x] = tile[threadIdx.x][threadIdx.y + i];
}

// ---------------- W hi/lo prep ----------------
__global__ void cvt_w_kernel(const float* __restrict__ W1, const float* __restrict__ W2) {
    int i = blockIdx.x * 256 + threadIdx.x;
    if (i < M1 * 384) {
        int r = i / 384, c = i % 384;
        float w = W1[i];
        __nv_bfloat16 h = bhi(w);
        g_W1s[r * W1ROW + c] = h;
        g_W1s[r * W1ROW + 384 + c] = blo(w, h);
    }
    if (i < M2 * 256) {
        int r = i / 256, c = i % 256;
        float w = W2[i];
        __nv_bfloat16 h = bhi(w);
        g_W2s[r * W2ROW + c] = h;
        g_W2s[r * W2ROW + 256 + c] = blo(w, h);
    }
}

// ---------------- points1 -> X1 cols[0..127]=hi, [384..511]=lo ----------------
__global__ void cvt_p1_kernel(const float* __restrict__ points1) {
    __shared__ float tile[32][33];
    int b = blockIdx.z, n0 = blockIdx.x * 32, c0 = blockIdx.y * 32;
    int tx = threadIdx.x & 31, ty = threadIdx.x >> 5;
    const float* src = points1 + (size_t)b * C1 * N1;
    #pragma unroll
    for (int i = 0; i < 32; i += 8)
        tile[ty + i][tx] = src[(size_t)(c0 + ty + i) * N1 + n0 + tx];
    __syncthreads();
    int p = threadIdx.x >> 3, g = threadIdx.x & 7;
    float f0 = tile[g * 4 + 0][p], f1 = tile[g * 4 + 1][p];
    float f2 = tile[g * 4 + 2][p], f3 = tile[g * 4 + 3][p];
    __nv_bfloat16 h0 = bhi(f0), h1 = bhi(f1), h2 = bhi(f2), h3 = bhi(f3);
    size_t row = (size_t)(b * N1 + n0 + p) * X1ROW;
    __nv_bfloat162 v;
    v.x = h0; v.y = h1; *(__nv_bfloat162*)&g_X1[row + c0 + g * 4] = v;
    v.x = h2; v.y = h3; *(__nv_bfloat162*)&g_X1[row + c0 + g * 4 + 2] = v;
    v.x = blo(f0, h0); v.y = blo(f1, h1); *(__nv_bfloat162*)&g_X1[row + 384 + c0 + g * 4] = v;
    v.x = blo(f2, h2); v.y = blo(f3, h3); *(__nv_bfloat162*)&g_X1[row + 384 + c0 + g * 4 + 2] = v;
}

// ---------------- 3-NN pass 1: quartered scan, paired f32x2 distances ----------------
__global__ void knn_kernel(const float* __restrict__ xyz1, const float* __restrict__ xyz2) {
    __shared__ float4 shA[512];           // (x0,x1,y0,y1) per pair
    __shared__ float4 shB[512];           // (z0,z1,|p0|^2,|p1|^2) per pair
    int b    = blockIdx.z;
    int half = blockIdx.y;                // quarter 0..3
    int n    = blockIdx.x * 256 + threadIdx.x;
    int base = half * 1024;
    const float* x1 = xyz1 + (size_t)b * 3 * N1;
    const float* x2 = xyz2 + (size_t)b * 3 * N2;
    for (int t = threadIdx.x; t < 512; t += 256) {
        int c0 = base + 2 * t, c1 = c0 + 1;
        float ax = x2[c0],          bx = x2[c1];
        float ay = x2[N2 + c0],     by = x2[N2 + c1];
        float az = x2[2 * N2 + c0], bz = x2[2 * N2 + c1];
        shA[t] = make_float4(ax, bx, ay, by);
        shB[t] = make_float4(az, bz,
                             ax * ax + ay * ay + az * az,
                             bx * bx + by * by + bz * bz);
    }
    float qx = x1[n], qy = x1[N1 + n], qz = x1[2 * N1 + n];
    unsigned long long M2X = dup2(-2.0f * qx);
    unsigned long long M2Y = dup2(-2.0f * qy);
    unsigned long long M2Z = dup2(-2.0f * qz);
    float d0 = 3.4e38f, d1 = 3.4e38f, d2 = 3.4e38f;
    int   i0 = 0, i1 = 0, i2 = 0;
    __syncthreads();
    #pragma unroll 4
    for (int j = 0; j < 512; j++) {
        float4 A = shA[j], B = shB[j];
        unsigned long long acc = pk2(B.z, B.w);        // norms
        fma2(acc, M2X, pk2(A.x, A.y));
        fma2(acc, M2Y, pk2(A.z, A.w));
        fma2(acc, M2Z, pk2(B.x, B.y));
        float2 r = up2(acc);
        if (r.x < d2) {
            bool b1 = r.x < d1, b0 = r.x < d0;
            int jg = base + 2 * j;
            d2 = b1 ? d1 : r.x;  i2 = b1 ? i1 : jg;
            d1 = b1 ? (b0 ? d0 : r.x) : d1;
            i1 = b1 ? (b0 ? i0 : jg) : i1;
            d0 = b0 ? r.x : d0;  i0 = b0 ? jg : i0;
        }
        if (r.y < d2) {
            bool b1 = r.y < d1, b0 = r.y < d0;
            int jg = base + 2 * j + 1;
            d2 = b1 ? d1 : r.y;  i2 = b1 ? i1 : jg;
            d1 = b1 ? (b0 ? d0 : r.y) : d1;
            i1 = b1 ? (b0 ? i0 : jg) : i1;
            d0 = b0 ? r.y : d0;  i0 = b0 ? jg : i0;
        }
    }
    int p = b * N1 + n;
    g_pd[(half * 3 + 0) * NTOT + p] = d0; g_pi[(half * 3 + 0) * NTOT + p] = i0;
    g_pd[(half * 3 + 1) * NTOT + p] = d1; g_pi[(half * 3 + 1) * NTOT + p] = i1;
    g_pd[(half * 3 + 2) * NTOT + p] = d2; g_pi[(half * 3 + 2) * NTOT + p] = i2;
}

// ---------------- 3-NN pass 2: merge 4 quarters, exact dists -> weights ----------------
__global__ void knn_merge_kernel(const float* __restrict__ xyz1, const float* __restrict__ xyz2) {
    int p = blockIdx.x * 256 + threadIdx.x;
    int b = p >> 14, n = p & (N1 - 1);
    float d0 = 3.4e38f, d1 = 3.4e38f, d2 = 3.4e38f;
    int   i0 = 0, i1 = 0, i2 = 0;
    #pragma unroll
    for (int e = 0; e < 12; e++) {        // quarters in order; entries sorted within
        float r = g_pd[e * NTOT + p];
        int  jg = g_pi[e * NTOT + p];
        if (r < d2) {
            bool b1 = r < d1, b0 = r < d0;
            d2 = b1 ? d1 : r;  i2 = b1 ? i1 : jg;
            d1 = b1 ? (b0 ? d0 : r) : d1;
            i1 = b1 ? (b0 ? i0 : jg) : i1;
            d0 = b0 ? r : d0;  i0 = b0 ? jg : i0;
        }
    }
    const float* x1 = xyz1 + (size_t)b * 3 * N1;
    const float* x2 = xyz2 + (size_t)b * 3 * N2;
    float qx = x1[n], qy = x1[N1 + n], qz = x1[2 * N1 + n];
    int   id[3] = { i0, i1, i2 };
    float w[3];
    #pragma unroll
    for (int t = 0; t < 3; t++) {
        float px = x2[id[t]], py = x2[N2 + id[t]], pz = x2[2 * N2 + id[t]];
        float dx = qx - px, dy = qy - py, dz = qz - pz;
        float dd = fmaxf(dx * dx + dy * dy + dz * dz, 1e-10f);
        w[t] = 1.0f / dd;
    }
    float ws = w[0] + w[1] + w[2];
    g_i0[p] = i0; g_i1[p] = i1; g_i2[p] = i2;
    g_w0[p] = w[0] / ws; g_w1[p] = w[1] / ws; g_w2[p] = w[2] / ws;
}

// ---------------- interp -> X1 cols[128..383]=hi, [512..767]=lo ----------------
__global__ void interp_kernel() {
    int p    = blockIdx.x * 8 + (threadIdx.x >> 5);
    int lane = threadIdx.x & 31;
    int b    = p >> 14;
    float w0 = g_w0[p], w1 = g_w1[p], w2 = g_w2[p];
    const float4* r0 = (const float4*)(g_p2t + ((size_t)b * N2 + g_i0[p]) * C2);
    const float4* r1 = (const float4*)(g_p2t + ((size_t)b * N2 + g_i1[p]) * C2);
    const float4* r2 = (const float4*)(g_p2t + ((size_t)b * N2 + g_i2[p]) * C2);
    size_t row = (size_t)p * X1ROW;
    int cA = lane, cB = lane + 32;
    float4 a0 = r0[cA], e0 = r1[cA], f0 = r2[cA];
    float4 a1 = r0[cB], e1 = r1[cB], f1 = r2[cB];
    #pragma unroll
    for (int it = 0; it < 2; it++) {
        float4 a = it ? a1 : a0, e = it ? e1 : e0, f = it ? f1 : f0;
        int c = it ? cB : cA;
        float ox = w0 * a.x + w1 * e.x + w2 * f.x;
        float oy = w0 * a.y + w1 * e.y + w2 * f.y;
        float oz = w0 * a.z + w1 * e.z + w2 * f.z;
        float ow = w0 * a.w + w1 * e.w + w2 * f.w;
        __nv_bfloat16 h0 = bhi(ox), h1 = bhi(oy), h2 = bhi(oz), h3 = bhi(ow);
        __nv_bfloat162 v;
        v.x = h0; v.y = h1; *(__nv_bfloat162*)&g_X1[row + 128 + 4 * c] = v;
        v.x = h2; v.y = h3; *(__nv_bfloat162*)&g_X1[row + 128 + 4 * c + 2] = v;
        v.x = blo(ox, h0); v.y = blo(oy, h1); *(__nv_bfloat162*)&g_X1[row + 512 + 4 * c] = v;
        v.x = blo(oz, h2); v.y = blo(ow, h3); *(__nv_bfloat162*)&g_X1[row + 512 + 4 * c + 2] = v;
    }
}

// ---------------- shared mainloop piece: one BK=32 chunk of HMMA ----------------
__device__ __forceinline__ void mma_chunk(uint32_t smA, uint32_t smB, int wn, int wm,
                                          int lane, float acc[2][8][4]) {
    uint32_t rsel = (uint32_t)(lane & 15);
    uint32_t csel = (uint32_t)(lane >> 4) * 16;
    #pragma unroll
    for (int ks = 0; ks < 2; ks++) {
        uint32_t af[2][4], bf[4][4];
        #pragma unroll
        for (int t = 0; t < 2; t++)
            LDM4(af[t], smA + (wn * 32 + t * 16 + rsel) * ROWB + ks * 32 + csel);
        #pragma unroll
        for (int jj = 0; jj < 4; jj++)
            LDM4(bf[jj], smB + (wm * 64 + jj * 16 + rsel) * ROWB + ks * 32 + csel);
        #pragma unroll
        for (int t = 0; t < 2; t++)
            #pragma unroll
            for (int j = 0; j < 8; j++)
                MMA(acc[t][j], af[t], bf[j >> 1][(j & 1)], bf[j >> 1][(j & 1) + 2]);
    }
}

// ---------------- GEMM1: Y1[n][m] = sum_k X1[n,k]*W1s[m,k]; 3-stage pipeline ----------------
__global__ __launch_bounds__(256) void gemm1_tc() {
    extern __shared__ char dsm[];
    uint32_t sb = smem_u32(dsm);
    int tid = threadIdx.x, lane = tid & 31, wid = tid >> 5;
    int wn = wid & 3, wm = wid >> 2;
    int m0 = blockIdx.x * 128, n0 = blockIdx.y * 128;   // x fastest -> m-pair shares n-tile in L2

    const __nv_bfloat16* Xb = g_X1  + (size_t)n0 * X1ROW;
    const __nv_bfloat16* Wb = g_W1s + (size_t)m0 * W1ROW;

    float acc[2][8][4];
    #pragma unroll
    for (int t = 0; t < 2; t++)
        #pragma unroll
        for (int j = 0; j < 8; j++)
            #pragma unroll
            for (int d = 0; d < 4; d++) acc[t][j][d] = 0.f;

    int row2 = tid >> 2, c4 = tid & 3;
    auto load = [&](int i) {
        int s = i % 3;
        int t = i / 12, kc = i % 12;
        int aoff = ((t == 1) ? 384 : 0) + kc * 32;
        int boff = ((t == 2) ? 384 : 0) + kc * 32;
        uint32_t dstA = sb + s * STAGEB;
        uint32_t dstB = dstA + TILEB;
        #pragma unroll
        for (int u = 0; u < 2; u++) {
            int r = row2 + u * 64;
            CP16(dstA + r * ROWB + c4 * 16, Xb + (size_t)r * X1ROW + aoff + c4 * 8);
            CP16(dstB + r * ROWB + c4 * 16, Wb + (size_t)r * W1ROW + boff + c4 * 8);
        }
        CPCOMMIT();
    };

    load(0); load(1);
    for (int i = 0; i < 36; i++) {
        if (i < 35) CPWAIT1(); else CPWAIT0();
        __syncthreads();
        if (i < 34) load(i + 2);
        int s = i % 3;
        mma_chunk(sb + s * STAGEB, sb + s * STAGEB + TILEB, wn, wm, lane, acc);
    }

    float* dst = g_Y1;
    #pragma unroll
    for (int t = 0; t < 2; t++) {
        #pragma unroll
        for (int j = 0; j < 8; j++) {
            int nr = n0 + wn * 32 + t * 16 + (lane >> 2);
            int mc = m0 + wm * 64 + j * 8 + (lane & 3) * 2;
            float2 v0 = make_float2(acc[t][j][0], acc[t][j][1]);
            float2 v1 = make_float2(acc[t][j][2], acc[t][j][3]);
            *(float2*)&dst[(size_t)nr * 256 + mc]       = v0;
            *(float2*)&dst[(size_t)(nr + 8) * 256 + mc] = v1;
        }
    }
    #pragma unroll
    for (int j = 0; j < 8; j++) {
        float s0 = 0.f, q0 = 0.f, s1 = 0.f, q1 = 0.f;
        #pragma unroll
        for (int t = 0; t < 2; t++) {
            s0 += acc[t][j][0] + acc[t][j][2];
            q0 += acc[t][j][0] * acc[t][j][0] + acc[t][j][2] * acc[t][j][2];
            s1 += acc[t][j][1] + acc[t][j][3];
            q1 += acc[t][j][1] * acc[t][j][1] + acc[t][j][3] * acc[t][j][3];
        }
        #pragma unroll
        for (int off = 4; off < 32; off <<= 1) {
            s0 += __shfl_xor_sync(0xffffffffu, s0, off);
            q0 += __shfl_xor_sync(0xffffffffu, q0, off);
            s1 += __shfl_xor_sync(0xffffffffu, s1, off);
            q1 += __shfl_xor_sync(0xffffffffu, q1, off);
        }
        if (lane < 4) {
            int mc = m0 + wm * 64 + j * 8 + lane * 2;
            atomicAdd(&g_sum1[mc], s0);  atomicAdd(&g_sq1[mc], q0);
            atomicAdd(&g_sum1[mc + 1], s1); atomicAdd(&g_sq1[mc + 1], q1);
        }
    }
}

// ---------------- finalize BN ----------------
__global__ void finalize1_kernel(const float* __restrict__ g1, const float* __restrict__ be1) {
    int i = threadIdx.x;
    float mean = g_sum1[i] * (1.0f / NTOT);
    float var  = g_sq1[i] * (1.0f / NTOT) - mean * mean;
    float sc   = g1[i] * rsqrtf(var + EPS_BN);
    g_scale1[i] = sc;
    g_shift1[i] = be1[i] - mean * sc;
}
__global__ void finalize2_kernel(const float* __restrict__ g2, const float* __restrict__ be2) {
    int i = threadIdx.x;
    float mean = g_sum2[i] * (1.0f / NTOT);
    float var  = g_sq2[i] * (1.0f / NTOT) - mean * mean;
    float sc   = g2[i] * rsqrtf(var + EPS_BN);
    g_scale2[i] = sc;
    g_shift2[i] = be2[i] - mean * sc;
}

// ---------------- mid: X2 = hi/lo split of relu(BN1(Y1)) ----------------
__global__ void mid_kernel() {
    __shared__ float sc[M1], sh[M1];
    int tid = threadIdx.x;
    sc[tid] = g_scale1[tid]; sh[tid] = g_shift1[tid];
    __syncthreads();
    int i4 = blockIdx.x * 256 + tid;
    int n = i4 >> 6, c = (i4 & 63) * 4;
    float4 v = *(const float4*)&g_Y1[(size_t)n * 256 + c];
    float y0 = fmaxf(fmaf(sc[c + 0], v.x, sh[c + 0]), 0.f);
    float y1 = fmaxf(fmaf(sc[c + 1], v.y, sh[c + 1]), 0.f);
    float y2 = fmaxf(fmaf(sc[c + 2], v.z, sh[c + 2]), 0.f);
    float y3 = fmaxf(fmaf(sc[c + 3], v.w, sh[c + 3]), 0.f);
    __nv_bfloat16 h0 = bhi(y0), h1 = bhi(y1), h2 = bhi(y2), h3 = bhi(y3);
    size_t row = (size_t)n * X2ROW;
    __nv_bfloat162 o;
    o.x = h0; o.y = h1; *(__nv_bfloat162*)&g_X2[row + c] = o;
    o.x = h2; o.y = h3; *(__nv_bfloat162*)&g_X2[row + c + 2] = o;
    o.x = blo(y0, h0); o.y = blo(y1, h1); *(__nv_bfloat162*)&g_X2[row + 256 + c] = o;
    o.x = blo(y2, h2); o.y = blo(y3, h3); *(__nv_bfloat162*)&g_X2[row + 256 + c + 2] = o;
}

// ---------------- GEMM2: out = W2s @ X2 (HMMA), 3-stage pipeline + 2-pass epilogue ----------------
__global__ __launch_bounds__(256) void gemm2_tc(float* __restrict__ out) {
    extern __shared__ char dsm[];
    uint32_t sb = smem_u32(dsm);
    int tid = threadIdx.x, lane = tid & 31, wid = tid >> 5;
    int wn = wid & 3, wm = wid >> 2;
    int n0 = blockIdx.x * 128;

    const __nv_bfloat16* Xb = g_X2 + (size_t)n0 * X2ROW;
    const __nv_bfloat16* Wb = g_W2s;

    float acc[2][8][4];
    #pragma unroll
    for (int t = 0; t < 2; t++)
        #pragma unroll
        for (int j = 0; j < 8; j++)
            #pragma unroll
            for (int d = 0; d < 4; d++) acc[t][j][d] = 0.f;

    int row2 = tid >> 2, c4 = tid & 3;
    auto load = [&](int i) {
        int s = i % 3;
        int t = i / 8, kc = i % 8;
        int aoff = ((t == 1) ? 256 : 0) + kc * 32;
        int boff = ((t == 2) ? 256 : 0) + kc * 32;
        uint32_t dstA = sb + s * STAGEB;
        uint32_t dstB = dstA + TILEB;
        #pragma unroll
        for (int u = 0; u < 2; u++) {
            int r = row2 + u * 64;
            CP16(dstA + r * ROWB + c4 * 16, Xb + (size_t)r * X2ROW + aoff + c4 * 8);
            CP16(dstB + r * ROWB + c4 * 16, Wb + (size_t)r * W2ROW + boff + c4 * 8);
        }
        CPCOMMIT();
    };

    load(0); load(1);
    for (int i = 0; i < 24; i++) {
        if (i < 23) CPWAIT1(); else CPWAIT0();
        __syncthreads();
        if (i < 22) load(i + 2);
        int s = i % 3;
        mma_chunk(sb + s * STAGEB, sb + s * STAGEB + TILEB, wn, wm, lane, acc);
    }

    // epilogue: two 64-channel passes through smem
    float* smT = (float*)dsm;
    int b = n0 >> 14, nn = n0 & (N1 - 1);
    #pragma unroll
    for (int h = 0; h < 2; h++) {
        __syncthreads();
        if (wm == h) {
            #pragma unroll
            for (int t = 0; t < 2; t++)
                #pragma unroll
                for (int j = 0; j < 8; j++) {
                    int nr = wn * 32 + t * 16 + (lane >> 2);
                    int ml = j * 8 + (lane & 3) * 2;
                    smT[(ml)     * 136 + nr]     = acc[t][j][0];
                    smT[(ml + 1) * 136 + nr]     = acc[t][j][1];
                    smT[(ml)     * 136 + nr + 8] = acc[t][j][2];
                    smT[(ml + 1) * 136 + nr + 8] = acc[t][j][3];
                }
        }
        __syncthreads();
        for (int m = wid; m < 64; m += 8) {
            float4 v = *(float4*)&smT[m * 136 + lane * 4];
            *(float4*)&out[((size_t)b * M2 + h * 64 + m) * N1 + nn + lane * 4] = v;
        }
    }
    // BN2 stats
    #pragma unroll
    for (int j = 0; j < 8; j++) {
        float s0 = 0.f, q0 = 0.f, s1 = 0.f, q1 = 0.f;
        #pragma unroll
        for (int t = 0; t < 2; t++) {
            s0 += acc[t][j][0] + acc[t][j][2];
            q0 += acc[t][j][0] * acc[t][j][0] + acc[t][j][2] * acc[t][j][2];
            s1 += acc[t][j][1] + acc[t][j][3];
            q1 += acc[t][j][1] * acc[t][j][1] + acc[t][j][3] * acc[t][j][3];
        }
        #pragma unroll
        for (int off = 4; off < 32; off <<= 1) {
            s0 += __shfl_xor_sync(0xffffffffu, s0, off);
            q0 += __shfl_xor_sync(0xffffffffu, q0, off);
            s1 += __shfl_xor_sync(0xffffffffu, s1, off);
            q1 += __shfl_xor_sync(0xffffffffu, q1, off);
        }
        if (lane < 4) {
            int mc = wm * 64 + j * 8 + lane * 2;
            atomicAdd(&g_sum2[mc], s0);  atomicAdd(&g_sq2[mc], q0);
            atomicAdd(&g_sum2[mc + 1], s1); atomicAdd(&g_sq2[mc + 1], q1);
        }
    }
}

// ---------------- final BN2 + relu in place ----------------
__global__ void bn2_kernel(float* __restrict__ out) {
    int i4 = blockIdx.x * 256 + threadIdx.x;
    int m  = (i4 >> 12) & 127;
    float s = g_scale2[m], t = g_shift2[m];
    float4 v = ((float4*)out)[i4];
    v.x = fmaxf(fmaf(s, v.x, t), 0.f);
    v.y = fmaxf(fmaf(s, v.y, t), 0.f);
    v.z = fmaxf(fmaf(s, v.z, t), 0.f);
    v.w = fmaxf(fmaf(s, v.w, t), 0.f);
    ((float4*)out)[i4] = v;
}

// ---------------- launcher ----------------
extern "C" void kernel_launch(void* const* d_in, const int* in_sizes, int n_in,
                              void* d_out, int out_size) {
    const float* xyz1    = (const float*)d_in[0];
    const float* xyz2    = (const float*)d_in[1];
    const float* points1 = (const float*)d_in[2];
    const float* points2 = (const float*)d_in[3];
    const float* W1      = (const float*)d_in[4];
    const float* g1      = (const float*)d_in[6];
    const float* be1     = (const float*)d_in[7];
    const float* W2      = (const float*)d_in[8];
    const float* g2      = (const float*)d_in[10];
    const float* be2     = (const float*)d_in[11];
    float* out = (float*)d_out;

    cudaFuncSetAttribute(gemm1_tc, cudaFuncAttributeMaxDynamicSharedMemorySize, SMEM_DYN);
    cudaFuncSetAttribute(gemm2_tc, cudaFuncAttributeMaxDynamicSharedMemorySize, SMEM_DYN);

    init_kernel<<<1, 256>>>();
    transpose_p2_kernel<<<dim3(N2 / 32, C2 / 32, BB), dim3(32, 8)>>>(points2);
    cvt_w_kernel<<<(M1 * 384) / 256, 256>>>(W1, W2);
    knn_kernel<<<dim3(N1 / 256, 4, BB), 256>>>(xyz1, xyz2);
    knn_merge_kernel<<<NTOT / 256, 256>>>(xyz1, xyz2);
    cvt_p1_kernel<<<dim3(N1 / 32, C1 / 32, BB), 256>>>(points1);
    interp_kernel<<<NTOT / 8, 256>>>();
    gemm1_tc<<<dim3(2, NTOT / 128), 256, SMEM_DYN>>>();
    finalize1_kernel<<<1, M1>>>(g1, be1);
    mid_kernel<<<(NTOT * 64) / 256, 256>>>();
    gemm2_tc<<<dim3(NTOT / 128, 1), 256, SMEM_DYN>>>(out);
    finalize2_kernel<<<1, M2>>>(g2, be2);
    bn2_kernel<<<(NTOT * M2 / 4) / 256, 256>>>(out);
}

// round 15
// speedup vs baseline: 1.4870x; 1.0061x over previous
#include <cuda_runtime.h>
#include <cuda_bf16.h>
#include <cstdint>

#define BB   4
#define N1   16384
#define N2   4096
#define C1   128
#define C2   256
#define M1   256
#define M2   128
#define NTOT 65536
#define EPS_BN 1e-5f

// K-stacked bf16 operand layouts (hi | lo)
#define X1ROW 768
#define W1ROW 768
#define X2ROW 512
#define W2ROW 512

// ---------------- scratch (static device globals) ----------------
__device__ __nv_bfloat16 g_X1[(size_t)NTOT * X1ROW];
__device__ __nv_bfloat16 g_X2[(size_t)NTOT * X2ROW];
__device__ __nv_bfloat16 g_W1s[M1 * W1ROW];
__device__ __nv_bfloat16 g_W2s[M2 * W2ROW];
__device__ float g_Y1[(size_t)NTOT * M1];
__device__ float g_p2t[BB * N2 * C2];
__device__ float g_pd[12 * NTOT];                     // per-quarter top3 r-vals
__device__ int   g_pi[12 * NTOT];
__device__ int   g_i0[NTOT], g_i1[NTOT], g_i2[NTOT];
__device__ float g_w0[NTOT], g_w1[NTOT], g_w2[NTOT];
__device__ float g_sum1[M1], g_sq1[M1], g_scale1[M1], g_shift1[M1];
__device__ float g_sum2[M2], g_sq2[M2], g_scale2[M2], g_shift2[M2];

// ---------------- helpers ----------------
__device__ __forceinline__ uint32_t smem_u32(const void* p) {
    uint32_t a;
    asm("{ .reg .u64 t; cvta.to.shared.u64 t, %1; cvt.u32.u64 %0, t; }" : "=r"(a) : "l"(p));
    return a;
}
#define CP16(dst, src) \
    asm volatile("cp.async.cg.shared.global [%0], [%1], 16;" :: "r"(dst), "l"(src) : "memory")
#define CPCOMMIT() asm volatile("cp.async.commit_group;" ::: "memory")
#define CPWAIT0()  asm volatile("cp.async.wait_group 0;" ::: "memory")
#define CPWAIT1()  asm volatile("cp.async.wait_group 1;" ::: "memory")

#define LDM4(r, addr) \
    asm volatile("ldmatrix.sync.aligned.m8n8.x4.shared.b16 {%0,%1,%2,%3}, [%4];" \
        : "=r"((r)[0]), "=r"((r)[1]), "=r"((r)[2]), "=r"((r)[3]) : "r"(addr))

#define MMA(d, a, b0, b1) \
    asm volatile("mma.sync.aligned.m16n8k16.row.col.f32.bf16.bf16.f32 " \
        "{%0,%1,%2,%3},{%4,%5,%6,%7},{%8,%9},{%0,%1,%2,%3};" \
        : "+f"((d)[0]), "+f"((d)[1]), "+f"((d)[2]), "+f"((d)[3]) \
        : "r"((a)[0]), "r"((a)[1]), "r"((a)[2]), "r"((a)[3]), "r"(b0), "r"(b1))

__device__ __forceinline__ __nv_bfloat16 bhi(float x) { return __float2bfloat16(x); }
__device__ __forceinline__ __nv_bfloat16 blo(float x, __nv_bfloat16 h) {
    return __float2bfloat16(x - __bfloat162float(h));
}

// f32x2 packed-FMA helpers (Blackwell)
__device__ __forceinline__ unsigned long long pk2(float lo, float hi) {
    unsigned long long r;
    asm("mov.b64 %0, {%1, %2};" : "=l"(r) : "f"(lo), "f"(hi));
    return r;
}
__device__ __forceinline__ unsigned long long dup2(float x) {
    unsigned long long r;
    asm("mov.b64 %0, {%1, %1};" : "=l"(r) : "f"(x));
    return r;
}
__device__ __forceinline__ void fma2(unsigned long long& d, unsigned long long a, unsigned long long b) {
    asm("fma.rn.f32x2 %0, %1, %2, %0;" : "+l"(d) : "l"(a), "l"(b));
}
__device__ __forceinline__ float2 up2(unsigned long long v) {
    float2 f;
    asm("mov.b64 {%0, %1}, %2;" : "=f"(f.x), "=f"(f.y) : "l"(v));
    return f;
}

#define ROWB   80
#define TILEB  10240
#define STAGEB 20480
#define SMEM_DYN 61440   // 3 mainloop stages; gemm2 epilogue 64x136x4=34816 fits; 2 CTAs/SM = 122.9KB

// ---------------- init ----------------
__global__ void init_kernel() {
    int t = threadIdx.x;
    if (t < M1) { g_sum1[t] = 0.f; g_sq1[t] = 0.f; }
    if (t < M2) { g_sum2[t] = 0.f; g_sq2[t] = 0.f; }
}

// ---------------- transpose points2 (B,C2,N2) -> (B,N2,C2) ----------------
__global__ void transpose_p2_kernel(const float* __restrict__ p2) {
    __shared__ float tile[32][33];
    int b = blockIdx.z, n0 = blockIdx.x * 32, c0 = blockIdx.y * 32;
    const float* src = p2 + (size_t)b * C2 * N2;
    #pragma unroll
    for (int i = 0; i < 32; i += 8)
        tile[threadIdx.y + i][threadIdx.x] = src[(size_t)(c0 + threadIdx.y + i) * N2 + n0 + threadIdx.x];
    __syncthreads();
    float* dst = g_p2t + (size_t)b * N2 * C2;
    #pragma unroll
    for (int i = 0; i < 32; i += 8)
        dst[(size_t)(n0 + threadIdx.y + i) * C2 + c0 + threadIdx.x] = tile[threadIdx.x][threadIdx.y + i];
}

// ---------------- W hi/lo prep ----------------
__global__ void cvt_w_kernel(const float* __restrict__ W1, const float* __restrict__ W2) {
    int i = blockIdx.x * 256 + threadIdx.x;
    if (i < M1 * 384) {
        int r = i / 384, c = i % 384;
        float w = W1[i];
        __nv_bfloat16 h = bhi(w);
        g_W1s[r * W1ROW + c] = h;
        g_W1s[r * W1ROW + 384 + c] = blo(w, h);
    }
    if (i < M2 * 256) {
        int r = i / 256, c = i % 256;
        float w = W2[i];
        __nv_bfloat16 h = bhi(w);
        g_W2s[r * W2ROW + c] = h;
        g_W2s[r * W2ROW + 256 + c] = blo(w, h);
    }
}

// ---------------- points1 -> X1 cols[0..127]=hi, [384..511]=lo ----------------
__global__ void cvt_p1_kernel(const float* __restrict__ points1) {
    __shared__ float tile[32][33];
    int b = blockIdx.z, n0 = blockIdx.x * 32, c0 = blockIdx.y * 32;
    int tx = threadIdx.x & 31, ty = threadIdx.x >> 5;
    const float* src = points1 + (size_t)b * C1 * N1;
    #pragma unroll
    for (int i = 0; i < 32; i += 8)
        tile[ty + i][tx] = src[(size_t)(c0 + ty + i) * N1 + n0 + tx];
    __syncthreads();
    int p = threadIdx.x >> 3, g = threadIdx.x & 7;
    float f0 = tile[g * 4 + 0][p], f1 = tile[g * 4 + 1][p];
    float f2 = tile[g * 4 + 2][p], f3 = tile[g * 4 + 3][p];
    __nv_bfloat16 h0 = bhi(f0), h1 = bhi(f1), h2 = bhi(f2), h3 = bhi(f3);
    size_t row = (size_t)(b * N1 + n0 + p) * X1ROW;
    __nv_bfloat162 v;
    v.x = h0; v.y = h1; *(__nv_bfloat162*)&g_X1[row + c0 + g * 4] = v;
    v.x = h2; v.y = h3; *(__nv_bfloat162*)&g_X1[row + c0 + g * 4 + 2] = v;
    v.x = blo(f0, h0); v.y = blo(f1, h1); *(__nv_bfloat162*)&g_X1[row + 384 + c0 + g * 4] = v;
    v.x = blo(f2, h2); v.y = blo(f3, h3); *(__nv_bfloat162*)&g_X1[row + 384 + c0 + g * 4 + 2] = v;
}

// ---------------- 3-NN pass 1: quartered scan, paired f32x2 distances ----------------
__global__ void knn_kernel(const float* __restrict__ xyz1, const float* __restrict__ xyz2) {
    __shared__ float4 shA[512];           // (x0,x1,y0,y1) per pair
    __shared__ float4 shB[512];           // (z0,z1,|p0|^2,|p1|^2) per pair
    int b    = blockIdx.z;
    int half = blockIdx.y;                // quarter 0..3
    int n    = blockIdx.x * 256 + threadIdx.x;
    int base = half * 1024;
    const float* x1 = xyz1 + (size_t)b * 3 * N1;
    const float* x2 = xyz2 + (size_t)b * 3 * N2;
    for (int t = threadIdx.x; t < 512; t += 256) {
        int c0 = base + 2 * t, c1 = c0 + 1;
        float ax = x2[c0],          bx = x2[c1];
        float ay = x2[N2 + c0],     by = x2[N2 + c1];
        float az = x2[2 * N2 + c0], bz = x2[2 * N2 + c1];
        shA[t] = make_float4(ax, bx, ay, by);
        shB[t] = make_float4(az, bz,
                             ax * ax + ay * ay + az * az,
                             bx * bx + by * by + bz * bz);
    }
    float qx = x1[n], qy = x1[N1 + n], qz = x1[2 * N1 + n];
    unsigned long long M2X = dup2(-2.0f * qx);
    unsigned long long M2Y = dup2(-2.0f * qy);
    unsigned long long M2Z = dup2(-2.0f * qz);
    float d0 = 3.4e38f, d1 = 3.4e38f, d2 = 3.4e38f;
    int   i0 = 0, i1 = 0, i2 = 0;
    __syncthreads();
    #pragma unroll 4
    for (int j = 0; j < 512; j++) {
        float4 A = shA[j], B = shB[j];
        unsigned long long acc = pk2(B.z, B.w);        // norms
        fma2(acc, M2X, pk2(A.x, A.y));
        fma2(acc, M2Y, pk2(A.z, A.w));
        fma2(acc, M2Z, pk2(B.x, B.y));
        float2 r = up2(acc);
        if (r.x < d2) {
            bool b1 = r.x < d1, b0 = r.x < d0;
            int jg = base + 2 * j;
            d2 = b1 ? d1 : r.x;  i2 = b1 ? i1 : jg;
            d1 = b1 ? (b0 ? d0 : r.x) : d1;
            i1 = b1 ? (b0 ? i0 : jg) : i1;
            d0 = b0 ? r.x : d0;  i0 = b0 ? jg : i0;
        }
        if (r.y < d2) {
            bool b1 = r.y < d1, b0 = r.y < d0;
            int jg = base + 2 * j + 1;
            d2 = b1 ? d1 : r.y;  i2 = b1 ? i1 : jg;
            d1 = b1 ? (b0 ? d0 : r.y) : d1;
            i1 = b1 ? (b0 ? i0 : jg) : i1;
            d0 = b0 ? r.y : d0;  i0 = b0 ? jg : i0;
        }
    }
    int p = b * N1 + n;
    g_pd[(half * 3 + 0) * NTOT + p] = d0; g_pi[(half * 3 + 0) * NTOT + p] = i0;
    g_pd[(half * 3 + 1) * NTOT + p] = d1; g_pi[(half * 3 + 1) * NTOT + p] = i1;
    g_pd[(half * 3 + 2) * NTOT + p] = d2; g_pi[(half * 3 + 2) * NTOT + p] = i2;
}

// ---------------- 3-NN pass 2: merge 4 quarters, exact dists -> weights ----------------
__global__ void knn_merge_kernel(const float* __restrict__ xyz1, const float* __restrict__ xyz2) {
    int p = blockIdx.x * 256 + threadIdx.x;
    int b = p >> 14, n = p & (N1 - 1);
    float d0 = 3.4e38f, d1 = 3.4e38f, d2 = 3.4e38f;
    int   i0 = 0, i1 = 0, i2 = 0;
    #pragma unroll
    for (int e = 0; e < 12; e++) {        // quarters in order; entries sorted within
        float r = g_pd[e * NTOT + p];
        int  jg = g_pi[e * NTOT + p];
        if (r < d2) {
            bool b1 = r < d1, b0 = r < d0;
            d2 = b1 ? d1 : r;  i2 = b1 ? i1 : jg;
            d1 = b1 ? (b0 ? d0 : r) : d1;
            i1 = b1 ? (b0 ? i0 : jg) : i1;
            d0 = b0 ? r : d0;  i0 = b0 ? jg : i0;
        }
    }
    const float* x1 = xyz1 + (size_t)b * 3 * N1;
    const float* x2 = xyz2 + (size_t)b * 3 * N2;
    float qx = x1[n], qy = x1[N1 + n], qz = x1[2 * N1 + n];
    int   id[3] = { i0, i1, i2 };
    float w[3];
    #pragma unroll
    for (int t = 0; t < 3; t++) {
        float px = x2[id[t]], py = x2[N2 + id[t]], pz = x2[2 * N2 + id[t]];
        float dx = qx - px, dy = qy - py, dz = qz - pz;
        float dd = fmaxf(dx * dx + dy * dy + dz * dz, 1e-10f);
        w[t] = 1.0f / dd;
    }
    float ws = w[0] + w[1] + w[2];
    g_i0[p] = i0; g_i1[p] = i1; g_i2[p] = i2;
    g_w0[p] = w[0] / ws; g_w1[p] = w[1] / ws; g_w2[p] = w[2] / ws;
}

// ---------------- interp -> X1 cols[128..383]=hi, [512..767]=lo ----------------
__global__ void interp_kernel() {
    int p    = blockIdx.x * 8 + (threadIdx.x >> 5);
    int lane = threadIdx.x & 31;
    int b    = p >> 14;
    float w0 = g_w0[p], w1 = g_w1[p], w2 = g_w2[p];
    const float4* r0 = (const float4*)(g_p2t + ((size_t)b * N2 + g_i0[p]) * C2);
    const float4* r1 = (const float4*)(g_p2t + ((size_t)b * N2 + g_i1[p]) * C2);
    const float4* r2 = (const float4*)(g_p2t + ((size_t)b * N2 + g_i2[p]) * C2);
    size_t row = (size_t)p * X1ROW;
    int cA = lane, cB = lane + 32;
    float4 a0 = r0[cA], e0 = r1[cA], f0 = r2[cA];
    float4 a1 = r0[cB], e1 = r1[cB], f1 = r2[cB];
    #pragma unroll
    for (int it = 0; it < 2; it++) {
        float4 a = it ? a1 : a0, e = it ? e1 : e0, f = it ? f1 : f0;
        int c = it ? cB : cA;
        float ox = w0 * a.x + w1 * e.x + w2 * f.x;
        float oy = w0 * a.y + w1 * e.y + w2 * f.y;
        float oz = w0 * a.z + w1 * e.z + w2 * f.z;
        float ow = w0 * a.w + w1 * e.w + w2 * f.w;
        __nv_bfloat16 h0 = bhi(ox), h1 = bhi(oy), h2 = bhi(oz), h3 = bhi(ow);
        __nv_bfloat162 v;
        v.x = h0; v.y = h1; *(__nv_bfloat162*)&g_X1[row + 128 + 4 * c] = v;
        v.x = h2; v.y = h3; *(__nv_bfloat162*)&g_X1[row + 128 + 4 * c + 2] = v;
        v.x = blo(ox, h0); v.y = blo(oy, h1); *(__nv_bfloat162*)&g_X1[row + 512 + 4 * c] = v;
        v.x = blo(oz, h2); v.y = blo(ow, h3); *(__nv_bfloat162*)&g_X1[row + 512 + 4 * c + 2] = v;
    }
}

// ---------------- shared mainloop piece: one BK=32 chunk of HMMA ----------------
__device__ __forceinline__ void mma_chunk(uint32_t smA, uint32_t smB, int wn, int wm,
                                          int lane, float acc[2][8][4]) {
    uint32_t rsel = (uint32_t)(lane & 15);
    uint32_t csel = (uint32_t)(lane >> 4) * 16;
    #pragma unroll
    for (int ks = 0; ks < 2; ks++) {
        uint32_t af[2][4], bf[4][4];
        #pragma unroll
        for (int t = 0; t < 2; t++)
            LDM4(af[t], smA + (wn * 32 + t * 16 + rsel) * ROWB + ks * 32 + csel);
        #pragma unroll
        for (int jj = 0; jj < 4; jj++)
            LDM4(bf[jj], smB + (wm * 64 + jj * 16 + rsel) * ROWB + ks * 32 + csel);
        #pragma unroll
        for (int t = 0; t < 2; t++)
            #pragma unroll
            for (int j = 0; j < 8; j++)
                MMA(acc[t][j], af[t], bf[j >> 1][(j & 1)], bf[j >> 1][(j & 1) + 2]);
    }
}

// ---------------- GEMM1: Y1[n][m] = sum_k X1[n,k]*W1s[m,k]; 3-stage pipeline, 2 CTA/SM ----------------
__global__ __launch_bounds__(256, 2) void gemm1_tc() {
    extern __shared__ char dsm[];
    uint32_t sb = smem_u32(dsm);
    int tid = threadIdx.x, lane = tid & 31, wid = tid >> 5;
    int wn = wid & 3, wm = wid >> 2;
    int m0 = blockIdx.x * 128, n0 = blockIdx.y * 128;   // x fastest -> m-pair shares n-tile in L2

    const __nv_bfloat16* Xb = g_X1  + (size_t)n0 * X1ROW;
    const __nv_bfloat16* Wb = g_W1s + (size_t)m0 * W1ROW;

    float acc[2][8][4];
    #pragma unroll
    for (int t = 0; t < 2; t++)
        #pragma unroll
        for (int j = 0; j < 8; j++)
            #pragma unroll
            for (int d = 0; d < 4; d++) acc[t][j][d] = 0.f;

    int row2 = tid >> 2, c4 = tid & 3;
    auto load = [&](int i) {
        int s = i % 3;
        int t = i / 12, kc = i % 12;
        int aoff = ((t == 1) ? 384 : 0) + kc * 32;
        int boff = ((t == 2) ? 384 : 0) + kc * 32;
        uint32_t dstA = sb + s * STAGEB;
        uint32_t dstB = dstA + TILEB;
        #pragma unroll
        for (int u = 0; u < 2; u++) {
            int r = row2 + u * 64;
            CP16(dstA + r * ROWB + c4 * 16, Xb + (size_t)r * X1ROW + aoff + c4 * 8);
            CP16(dstB + r * ROWB + c4 * 16, Wb + (size_t)r * W1ROW + boff + c4 * 8);
        }
        CPCOMMIT();
    };

    load(0); load(1);
    for (int i = 0; i < 36; i++) {
        if (i < 35) CPWAIT1(); else CPWAIT0();
        __syncthreads();
        if (i < 34) load(i + 2);
        int s = i % 3;
        mma_chunk(sb + s * STAGEB, sb + s * STAGEB + TILEB, wn, wm, lane, acc);
    }

    float* dst = g_Y1;
    #pragma unroll
    for (int t = 0; t < 2; t++) {
        #pragma unroll
        for (int j = 0; j < 8; j++) {
            int nr = n0 + wn * 32 + t * 16 + (lane >> 2);
            int mc = m0 + wm * 64 + j * 8 + (lane & 3) * 2;
            float2 v0 = make_float2(acc[t][j][0], acc[t][j][1]);
            float2 v1 = make_float2(acc[t][j][2], acc[t][j][3]);
            *(float2*)&dst[(size_t)nr * 256 + mc]       = v0;
            *(float2*)&dst[(size_t)(nr + 8) * 256 + mc] = v1;
        }
    }
    #pragma unroll
    for (int j = 0; j < 8; j++) {
        float s0 = 0.f, q0 = 0.f, s1 = 0.f, q1 = 0.f;
        #pragma unroll
        for (int t = 0; t < 2; t++) {
            s0 += acc[t][j][0] + acc[t][j][2];
            q0 += acc[t][j][0] * acc[t][j][0] + acc[t][j][2] * acc[t][j][2];
            s1 += acc[t][j][1] + acc[t][j][3];
            q1 += acc[t][j][1] * acc[t][j][1] + acc[t][j][3] * acc[t][j][3];
        }
        #pragma unroll
        for (int off = 4; off < 32; off <<= 1) {
            s0 += __shfl_xor_sync(0xffffffffu, s0, off);
            q0 += __shfl_xor_sync(0xffffffffu, q0, off);
            s1 += __shfl_xor_sync(0xffffffffu, s1, off);
            q1 += __shfl_xor_sync(0xffffffffu, q1, off);
        }
        if (lane < 4) {
            int mc = m0 + wm * 64 + j * 8 + lane * 2;
            atomicAdd(&g_sum1[mc], s0);  atomicAdd(&g_sq1[mc], q0);
            atomicAdd(&g_sum1[mc + 1], s1); atomicAdd(&g_sq1[mc + 1], q1);
        }
    }
}

// ---------------- finalize BN ----------------
__global__ void finalize1_kernel(const float* __restrict__ g1, const float* __restrict__ be1) {
    int i = threadIdx.x;
    float mean = g_sum1[i] * (1.0f / NTOT);
    float var  = g_sq1[i] * (1.0f / NTOT) - mean * mean;
    float sc   = g1[i] * rsqrtf(var + EPS_BN);
    g_scale1[i] = sc;
    g_shift1[i] = be1[i] - mean * sc;
}
__global__ void finalize2_kernel(const float* __restrict__ g2, const float* __restrict__ be2) {
    int i = threadIdx.x;
    float mean = g_sum2[i] * (1.0f / NTOT);
    float var  = g_sq2[i] * (1.0f / NTOT) - mean * mean;
    float sc   = g2[i] * rsqrtf(var + EPS_BN);
    g_scale2[i] = sc;
    g_shift2[i] = be2[i] - mean * sc;
}

// ---------------- mid: X2 = hi/lo split of relu(BN1(Y1)) ----------------
__global__ void mid_kernel() {
    __shared__ float sc[M1], sh[M1];
    int tid = threadIdx.x;
    sc[tid] = g_scale1[tid]; sh[tid] = g_shift1[tid];
    __syncthreads();
    int i4 = blockIdx.x * 256 + tid;
    int n = i4 >> 6, c = (i4 & 63) * 4;
    float4 v = *(const float4*)&g_Y1[(size_t)n * 256 + c];
    float y0 = fmaxf(fmaf(sc[c + 0], v.x, sh[c + 0]), 0.f);
    float y1 = fmaxf(fmaf(sc[c + 1], v.y, sh[c + 1]), 0.f);
    float y2 = fmaxf(fmaf(sc[c + 2], v.z, sh[c + 2]), 0.f);
    float y3 = fmaxf(fmaf(sc[c + 3], v.w, sh[c + 3]), 0.f);
    __nv_bfloat16 h0 = bhi(y0), h1 = bhi(y1), h2 = bhi(y2), h3 = bhi(y3);
    size_t row = (size_t)n * X2ROW;
    __nv_bfloat162 o;
    o.x = h0; o.y = h1; *(__nv_bfloat162*)&g_X2[row + c] = o;
    o.x = h2; o.y = h3; *(__nv_bfloat162*)&g_X2[row + c + 2] = o;
    o.x = blo(y0, h0); o.y = blo(y1, h1); *(__nv_bfloat162*)&g_X2[row + 256 + c] = o;
    o.x = blo(y2, h2); o.y = blo(y3, h3); *(__nv_bfloat162*)&g_X2[row + 256 + c + 2] = o;
}

// ---------------- GEMM2: out = W2s @ X2 (HMMA), 3-stage pipeline, 2 CTA/SM ----------------
__global__ __launch_bounds__(256, 2) void gemm2_tc(float* __restrict__ out) {
    extern __shared__ char dsm[];
    uint32_t sb = smem_u32(dsm);
    int tid = threadIdx.x, lane = tid & 31, wid = tid >> 5;
    int wn = wid & 3, wm = wid >> 2;
    int n0 = blockIdx.x * 128;

    const __nv_bfloat16* Xb = g_X2 + (size_t)n0 * X2ROW;
    const __nv_bfloat16* Wb = g_W2s;

    float acc[2][8][4];
    #pragma unroll
    for (int t = 0; t < 2; t++)
        #pragma unroll
        for (int j = 0; j < 8; j++)
            #pragma unroll
            for (int d = 0; d < 4; d++) acc[t][j][d] = 0.f;

    int row2 = tid >> 2, c4 = tid & 3;
    auto load = [&](int i) {
        int s = i % 3;
        int t = i / 8, kc = i % 8;
        int aoff = ((t == 1) ? 256 : 0) + kc * 32;
        int boff = ((t == 2) ? 256 : 0) + kc * 32;
        uint32_t dstA = sb + s * STAGEB;
        uint32_t dstB = dstA + TILEB;
        #pragma unroll
        for (int u = 0; u < 2; u++) {
            int r = row2 + u * 64;
            CP16(dstA + r * ROWB + c4 * 16, Xb + (size_t)r * X2ROW + aoff + c4 * 8);
            CP16(dstB + r * ROWB + c4 * 16, Wb + (size_t)r * W2ROW + boff + c4 * 8);
        }
        CPCOMMIT();
    };

    load(0); load(1);
    for (int i = 0; i < 24; i++) {
        if (i < 23) CPWAIT1(); else CPWAIT0();
        __syncthreads();
        if (i < 22) load(i + 2);
        int s = i % 3;
        mma_chunk(sb + s * STAGEB, sb + s * STAGEB + TILEB, wn, wm, lane, acc);
    }

    // epilogue: two 64-channel passes through smem
    float* smT = (float*)dsm;
    int b = n0 >> 14, nn = n0 & (N1 - 1);
    #pragma unroll
    for (int h = 0; h < 2; h++) {
        __syncthreads();
        if (wm == h) {
            #pragma unroll
            for (int t = 0; t < 2; t++)
                #pragma unroll
                for (int j = 0; j < 8; j++) {
                    int nr = wn * 32 + t * 16 + (lane >> 2);
                    int ml = j * 8 + (lane & 3) * 2;
                    smT[(ml)     * 136 + nr]     = acc[t][j][0];
                    smT[(ml + 1) * 136 + nr]     = acc[t][j][1];
                    smT[(ml)     * 136 + nr + 8] = acc[t][j][2];
                    smT[(ml + 1) * 136 + nr + 8] = acc[t][j][3];
                }
        }
        __syncthreads();
        for (int m = wid; m < 64; m += 8) {
            float4 v = *(float4*)&smT[m * 136 + lane * 4];
            *(float4*)&out[((size_t)b * M2 + h * 64 + m) * N1 + nn + lane * 4] = v;
        }
    }
    // BN2 stats
    #pragma unroll
    for (int j = 0; j < 8; j++) {
        float s0 = 0.f, q0 = 0.f, s1 = 0.f, q1 = 0.f;
        #pragma unroll
        for (int t = 0; t < 2; t++) {
            s0 += acc[t][j][0] + acc[t][j][2];
            q0 += acc[t][j][0] * acc[t][j][0] + acc[t][j][2] * acc[t][j][2];
            s1 += acc[t][j][1] + acc[t][j][3];
            q1 += acc[t][j][1] * acc[t][j][1] + acc[t][j][3] * acc[t][j][3];
        }
        #pragma unroll
        for (int off = 4; off < 32; off <<= 1) {
            s0 += __shfl_xor_sync(0xffffffffu, s0, off);
            q0 += __shfl_xor_sync(0xffffffffu, q0, off);
            s1 += __shfl_xor_sync(0xffffffffu, s1, off);
            q1 += __shfl_xor_sync(0xffffffffu, q1, off);
        }
        if (lane < 4) {
            int mc = wm * 64 + j * 8 + lane * 2;
            atomicAdd(&g_sum2[mc], s0);  atomicAdd(&g_sq2[mc], q0);
            atomicAdd(&g_sum2[mc + 1], s1); atomicAdd(&g_sq2[mc + 1], q1);
        }
    }
}

// ---------------- final BN2 + relu in place ----------------
__global__ void bn2_kernel(float* __restrict__ out) {
    int i4 = blockIdx.x * 256 + threadIdx.x;
    int m  = (i4 >> 12) & 127;
    float s = g_scale2[m], t = g_shift2[m];
    float4 v = ((float4*)out)[i4];
    v.x = fmaxf(fmaf(s, v.x, t), 0.f);
    v.y = fmaxf(fmaf(s, v.y, t), 0.f);
    v.z = fmaxf(fmaf(s, v.z, t), 0.f);
    v.w = fmaxf(fmaf(s, v.w, t), 0.f);
    ((float4*)out)[i4] = v;
}

// ---------------- launcher ----------------
extern "C" void kernel_launch(void* const* d_in, const int* in_sizes, int n_in,
                              void* d_out, int out_size) {
    const float* xyz1    = (const float*)d_in[0];
    const float* xyz2    = (const float*)d_in[1];
    const float* points1 = (const float*)d_in[2];
    const float* points2 = (const float*)d_in[3];
    const float* W1      = (const float*)d_in[4];
    const float* g1      = (const float*)d_in[6];
    const float* be1     = (const float*)d_in[7];
    const float* W2      = (const float*)d_in[8];
    const float* g2      = (const float*)d_in[10];
    const float* be2     = (const float*)d_in[11];
    float* out = (float*)d_out;

    cudaFuncSetAttribute(gemm1_tc, cudaFuncAttributeMaxDynamicSharedMemorySize, SMEM_DYN);
    cudaFuncSetAttribute(gemm2_tc, cudaFuncAttributeMaxDynamicSharedMemorySize, SMEM_DYN);

    init_kernel<<<1, 256>>>();
    transpose_p2_kernel<<<dim3(N2 / 32, C2 / 32, BB), dim3(32, 8)>>>(points2);
    cvt_w_kernel<<<(M1 * 384) / 256, 256>>>(W1, W2);
    knn_kernel<<<dim3(N1 / 256, 4, BB), 256>>>(xyz1, xyz2);
    knn_merge_kernel<<<NTOT / 256, 256>>>(xyz1, xyz2);
    cvt_p1_kernel<<<dim3(N1 / 32, C1 / 32, BB), 256>>>(points1);
    interp_kernel<<<NTOT / 8, 256>>>();
    gemm1_tc<<<dim3(2, NTOT / 128), 256, SMEM_DYN>>>();
    finalize1_kernel<<<1, M1>>>(g1, be1);
    mid_kernel<<<(NTOT * 64) / 256, 256>>>();
    gemm2_tc<<<dim3(NTOT / 128, 1), 256, SMEM_DYN>>>(out);
    finalize2_kernel<<<1, M2>>>(g2, be2);
    bn2_kernel<<<(NTOT * M2 / 4) / 256, 256>>>(out);
}

// round 16
// speedup vs baseline: 1.6057x; 1.0798x over previous
#include <cuda_runtime.h>
#include <cuda_bf16.h>
#include <cstdint>

#define BB   4
#define N1   16384
#define N2   4096
#define C1   128
#define C2   256
#define M1   256
#define M2   128
#define NTOT 65536
#define EPS_BN 1e-5f

// K-stacked bf16 operand layouts (hi | lo)
#define X1ROW 768
#define W1ROW 768
#define X2ROW 512
#define W2ROW 512

// ---------------- scratch (static device globals) ----------------
__device__ __nv_bfloat16 g_X1[(size_t)NTOT * X1ROW];
__device__ __nv_bfloat16 g_X2[(size_t)NTOT * X2ROW];
__device__ __nv_bfloat16 g_W1s[M1 * W1ROW];
__device__ __nv_bfloat16 g_W2s[M2 * W2ROW];
__device__ float g_Y1[(size_t)NTOT * M1];
__device__ float g_p2t[BB * N2 * C2];
__device__ float g_pd[12 * NTOT];                     // per-quarter top3 r-vals
__device__ int   g_pi[12 * NTOT];
__device__ int   g_i0[NTOT], g_i1[NTOT], g_i2[NTOT];
__device__ float g_w0[NTOT], g_w1[NTOT], g_w2[NTOT];
__device__ float g_sum1[M1], g_sq1[M1], g_scale1[M1], g_shift1[M1];
__device__ float g_sum2[M2], g_sq2[M2], g_scale2[M2], g_shift2[M2];

// ---------------- helpers ----------------
__device__ __forceinline__ uint32_t smem_u32(const void* p) {
    uint32_t a;
    asm("{ .reg .u64 t; cvta.to.shared.u64 t, %1; cvt.u32.u64 %0, t; }" : "=r"(a) : "l"(p));
    return a;
}
#define CP16(dst, src) \
    asm volatile("cp.async.cg.shared.global [%0], [%1], 16;" :: "r"(dst), "l"(src) : "memory")
#define CPCOMMIT() asm volatile("cp.async.commit_group;" ::: "memory")
#define CPWAIT0()  asm volatile("cp.async.wait_group 0;" ::: "memory")

#define LDM4(r, addr) \
    asm volatile("ldmatrix.sync.aligned.m8n8.x4.shared.b16 {%0,%1,%2,%3}, [%4];" \
        : "=r"((r)[0]), "=r"((r)[1]), "=r"((r)[2]), "=r"((r)[3]) : "r"(addr))

#define MMA(d, a, b0, b1) \
    asm volatile("mma.sync.aligned.m16n8k16.row.col.f32.bf16.bf16.f32 " \
        "{%0,%1,%2,%3},{%4,%5,%6,%7},{%8,%9},{%0,%1,%2,%3};" \
        : "+f"((d)[0]), "+f"((d)[1]), "+f"((d)[2]), "+f"((d)[3]) \
        : "r"((a)[0]), "r"((a)[1]), "r"((a)[2]), "r"((a)[3]), "r"(b0), "r"(b1))

__device__ __forceinline__ __nv_bfloat16 bhi(float x) { return __float2bfloat16(x); }
__device__ __forceinline__ __nv_bfloat16 blo(float x, __nv_bfloat16 h) {
    return __float2bfloat16(x - __bfloat162float(h));
}

// f32x2 packed-FMA helpers (Blackwell)
__device__ __forceinline__ unsigned long long pk2(float lo, float hi) {
    unsigned long long r;
    asm("mov.b64 %0, {%1, %2};" : "=l"(r) : "f"(lo), "f"(hi));
    return r;
}
__device__ __forceinline__ unsigned long long dup2(float x) {
    unsigned long long r;
    asm("mov.b64 %0, {%1, %1};" : "=l"(r) : "f"(x));
    return r;
}
__device__ __forceinline__ void fma2(unsigned long long& d, unsigned long long a, unsigned long long b) {
    asm("fma.rn.f32x2 %0, %1, %2, %0;" : "+l"(d) : "l"(a), "l"(b));
}
__device__ __forceinline__ float2 up2(unsigned long long v) {
    float2 f;
    asm("mov.b64 {%0, %1}, %2;" : "=f"(f.x), "=f"(f.y) : "l"(v));
    return f;
}

// BK=64 smem geometry: row = 64 bf16 = 128B + 16B pad = 144B (conflict-free ldmatrix)
#define ROW2B   144
#define TILE2B  18432
#define STAGE2B 36864
#define SMEM_DYN 73728   // 2 stages; gemm2 epilogue 64x136x4=34816 fits; 2 CTAs/SM = 147KB

// ---------------- init ----------------
__global__ void init_kernel() {
    int t = threadIdx.x;
    if (t < M1) { g_sum1[t] = 0.f; g_sq1[t] = 0.f; }
    if (t < M2) { g_sum2[t] = 0.f; g_sq2[t] = 0.f; }
}

// ---------------- transpose points2 (B,C2,N2) -> (B,N2,C2) ----------------
__global__ void transpose_p2_kernel(const float* __restrict__ p2) {
    __shared__ float tile[32][33];
    int b = blockIdx.z, n0 = blockIdx.x * 32, c0 = blockIdx.y * 32;
    const float* src = p2 + (size_t)b * C2 * N2;
    #pragma unroll
    for (int i = 0; i < 32; i += 8)
        tile[threadIdx.y + i][threadIdx.x] = src[(size_t)(c0 + threadIdx.y + i) * N2 + n0 + threadIdx.x];
    __syncthreads();
    float* dst = g_p2t + (size_t)b * N2 * C2;
    #pragma unroll
    for (int i = 0; i < 32; i += 8)
        dst[(size_t)(n0 + threadIdx.y + i) * C2 + c0 + threadIdx.x] = tile[threadIdx.x][threadIdx.y + i];
}

// ---------------- W hi/lo prep ----------------
__global__ void cvt_w_kernel(const float* __restrict__ W1, const float* __restrict__ W2) {
    int i = blockIdx.x * 256 + threadIdx.x;
    if (i < M1 * 384) {
        int r = i / 384, c = i % 384;
        float w = W1[i];
        __nv_bfloat16 h = bhi(w);
        g_W1s[r * W1ROW + c] = h;
        g_W1s[r * W1ROW + 384 + c] = blo(w, h);
    }
    if (i < M2 * 256) {
        int r = i / 256, c = i % 256;
        float w = W2[i];
        __nv_bfloat16 h = bhi(w);
        g_W2s[r * W2ROW + c] = h;
        g_W2s[r * W2ROW + 256 + c] = blo(w, h);
    }
}

// ---------------- points1 -> X1 cols[0..127]=hi, [384..511]=lo ----------------
__global__ void cvt_p1_kernel(const float* __restrict__ points1) {
    __shared__ float tile[32][33];
    int b = blockIdx.z, n0 = blockIdx.x * 32, c0 = blockIdx.y * 32;
    int tx = threadIdx.x & 31, ty = threadIdx.x >> 5;
    const float* src = points1 + (size_t)b * C1 * N1;
    #pragma unroll
    for (int i = 0; i < 32; i += 8)
        tile[ty + i][tx] = src[(size_t)(c0 + ty + i) * N1 + n0 + tx];
    __syncthreads();
    int p = threadIdx.x >> 3, g = threadIdx.x & 7;
    float f0 = tile[g * 4 + 0][p], f1 = tile[g * 4 + 1][p];
    float f2 = tile[g * 4 + 2][p], f3 = tile[g * 4 + 3][p];
    __nv_bfloat16 h0 = bhi(f0), h1 = bhi(f1), h2 = bhi(f2), h3 = bhi(f3);
    size_t row = (size_t)(b * N1 + n0 + p) * X1ROW;
    __nv_bfloat162 v;
    v.x = h0; v.y = h1; *(__nv_bfloat162*)&g_X1[row + c0 + g * 4] = v;
    v.x = h2; v.y = h3; *(__nv_bfloat162*)&g_X1[row + c0 + g * 4 + 2] = v;
    v.x = blo(f0, h0); v.y = blo(f1, h1); *(__nv_bfloat162*)&g_X1[row + 384 + c0 + g * 4] = v;
    v.x = blo(f2, h2); v.y = blo(f3, h3); *(__nv_bfloat162*)&g_X1[row + 384 + c0 + g * 4 + 2] = v;
}

// ---------------- 3-NN pass 1: quartered scan, paired f32x2 distances ----------------
__global__ void knn_kernel(const float* __restrict__ xyz1, const float* __restrict__ xyz2) {
    __shared__ float4 shA[512];           // (x0,x1,y0,y1) per pair
    __shared__ float4 shB[512];           // (z0,z1,|p0|^2,|p1|^2) per pair
    int b    = blockIdx.z;
    int half = blockIdx.y;                // quarter 0..3
    int n    = blockIdx.x * 256 + threadIdx.x;
    int base = half * 1024;
    const float* x1 = xyz1 + (size_t)b * 3 * N1;
    const float* x2 = xyz2 + (size_t)b * 3 * N2;
    for (int t = threadIdx.x; t < 512; t += 256) {
        int c0 = base + 2 * t, c1 = c0 + 1;
        float ax = x2[c0],          bx = x2[c1];
        float ay = x2[N2 + c0],     by = x2[N2 + c1];
        float az = x2[2 * N2 + c0], bz = x2[2 * N2 + c1];
        shA[t] = make_float4(ax, bx, ay, by);
        shB[t] = make_float4(az, bz,
                             ax * ax + ay * ay + az * az,
                             bx * bx + by * by + bz * bz);
    }
    float qx = x1[n], qy = x1[N1 + n], qz = x1[2 * N1 + n];
    unsigned long long M2X = dup2(-2.0f * qx);
    unsigned long long M2Y = dup2(-2.0f * qy);
    unsigned long long M2Z = dup2(-2.0f * qz);
    float d0 = 3.4e38f, d1 = 3.4e38f, d2 = 3.4e38f;
    int   i0 = 0, i1 = 0, i2 = 0;
    __syncthreads();
    #pragma unroll 4
    for (int j = 0; j < 512; j++) {
        float4 A = shA[j], B = shB[j];
        unsigned long long acc = pk2(B.z, B.w);        // norms
        fma2(acc, M2X, pk2(A.x, A.y));
        fma2(acc, M2Y, pk2(A.z, A.w));
        fma2(acc, M2Z, pk2(B.x, B.y));
        float2 r = up2(acc);
        if (r.x < d2) {
            bool b1 = r.x < d1, b0 = r.x < d0;
            int jg = base + 2 * j;
            d2 = b1 ? d1 : r.x;  i2 = b1 ? i1 : jg;
            d1 = b1 ? (b0 ? d0 : r.x) : d1;
            i1 = b1 ? (b0 ? i0 : jg) : i1;
            d0 = b0 ? r.x : d0;  i0 = b0 ? jg : i0;
        }
        if (r.y < d2) {
            bool b1 = r.y < d1, b0 = r.y < d0;
            int jg = base + 2 * j + 1;
            d2 = b1 ? d1 : r.y;  i2 = b1 ? i1 : jg;
            d1 = b1 ? (b0 ? d0 : r.y) : d1;
            i1 = b1 ? (b0 ? i0 : jg) : i1;
            d0 = b0 ? r.y : d0;  i0 = b0 ? jg : i0;
        }
    }
    int p = b * N1 + n;
    g_pd[(half * 3 + 0) * NTOT + p] = d0; g_pi[(half * 3 + 0) * NTOT + p] = i0;
    g_pd[(half * 3 + 1) * NTOT + p] = d1; g_pi[(half * 3 + 1) * NTOT + p] = i1;
    g_pd[(half * 3 + 2) * NTOT + p] = d2; g_pi[(half * 3 + 2) * NTOT + p] = i2;
}

// ---------------- 3-NN pass 2: merge 4 quarters, exact dists -> weights ----------------
__global__ void knn_merge_kernel(const float* __restrict__ xyz1, const float* __restrict__ xyz2) {
    int p = blockIdx.x * 256 + threadIdx.x;
    int b = p >> 14, n = p & (N1 - 1);
    float d0 = 3.4e38f, d1 = 3.4e38f, d2 = 3.4e38f;
    int   i0 = 0, i1 = 0, i2 = 0;
    #pragma unroll
    for (int e = 0; e < 12; e++) {        // quarters in order; entries sorted within
        float r = g_pd[e * NTOT + p];
        int  jg = g_pi[e * NTOT + p];
        if (r < d2) {
            bool b1 = r < d1, b0 = r < d0;
            d2 = b1 ? d1 : r;  i2 = b1 ? i1 : jg;
            d1 = b1 ? (b0 ? d0 : r) : d1;
            i1 = b1 ? (b0 ? i0 : jg) : i1;
            d0 = b0 ? r : d0;  i0 = b0 ? jg : i0;
        }
    }
    const float* x1 = xyz1 + (size_t)b * 3 * N1;
    const float* x2 = xyz2 + (size_t)b * 3 * N2;
    float qx = x1[n], qy = x1[N1 + n], qz = x1[2 * N1 + n];
    int   id[3] = { i0, i1, i2 };
    float w[3];
    #pragma unroll
    for (int t = 0; t < 3; t++) {
        float px = x2[id[t]], py = x2[N2 + id[t]], pz = x2[2 * N2 + id[t]];
        float dx = qx - px, dy = qy - py, dz = qz - pz;
        float dd = fmaxf(dx * dx + dy * dy + dz * dz, 1e-10f);
        w[t] = 1.0f / dd;
    }
    float ws = w[0] + w[1] + w[2];
    g_i0[p] = i0; g_i1[p] = i1; g_i2[p] = i2;
    g_w0[p] = w[0] / ws; g_w1[p] = w[1] / ws; g_w2[p] = w[2] / ws;
}

// ---------------- interp -> X1 cols[128..383]=hi, [512..767]=lo ----------------
__global__ void interp_kernel() {
    int p    = blockIdx.x * 8 + (threadIdx.x >> 5);
    int lane = threadIdx.x & 31;
    int b    = p >> 14;
    float w0 = g_w0[p], w1 = g_w1[p], w2 = g_w2[p];
    const float4* r0 = (const float4*)(g_p2t + ((size_t)b * N2 + g_i0[p]) * C2);
    const float4* r1 = (const float4*)(g_p2t + ((size_t)b * N2 + g_i1[p]) * C2);
    const float4* r2 = (const float4*)(g_p2t + ((size_t)b * N2 + g_i2[p]) * C2);
    size_t row = (size_t)p * X1ROW;
    int cA = lane, cB = lane + 32;
    float4 a0 = r0[cA], e0 = r1[cA], f0 = r2[cA];
    float4 a1 = r0[cB], e1 = r1[cB], f1 = r2[cB];
    #pragma unroll
    for (int it = 0; it < 2; it++) {
        float4 a = it ? a1 : a0, e = it ? e1 : e0, f = it ? f1 : f0;
        int c = it ? cB : cA;
        float ox = w0 * a.x + w1 * e.x + w2 * f.x;
        float oy = w0 * a.y + w1 * e.y + w2 * f.y;
        float oz = w0 * a.z + w1 * e.z + w2 * f.z;
        float ow = w0 * a.w + w1 * e.w + w2 * f.w;
        __nv_bfloat16 h0 = bhi(ox), h1 = bhi(oy), h2 = bhi(oz), h3 = bhi(ow);
        __nv_bfloat162 v;
        v.x = h0; v.y = h1; *(__nv_bfloat162*)&g_X1[row + 128 + 4 * c] = v;
        v.x = h2; v.y = h3; *(__nv_bfloat162*)&g_X1[row + 128 + 4 * c + 2] = v;
        v.x = blo(ox, h0); v.y = blo(oy, h1); *(__nv_bfloat162*)&g_X1[row + 512 + 4 * c] = v;
        v.x = blo(oz, h2); v.y = blo(ow, h3); *(__nv_bfloat162*)&g_X1[row + 512 + 4 * c + 2] = v;
    }
}

// ---------------- one BK=64 chunk of HMMA (4 k-steps of 16) ----------------
__device__ __forceinline__ void mma_chunk64(uint32_t smA, uint32_t smB, int wn, int wm,
                                            int lane, float acc[2][8][4]) {
    uint32_t rsel = (uint32_t)(lane & 15);
    uint32_t csel = (uint32_t)(lane >> 4) * 16;
    #pragma unroll
    for (int ks = 0; ks < 4; ks++) {
        uint32_t af[2][4], bf[4][4];
        #pragma unroll
        for (int t = 0; t < 2; t++)
            LDM4(af[t], smA + (wn * 32 + t * 16 + rsel) * ROW2B + ks * 32 + csel);
        #pragma unroll
        for (int jj = 0; jj < 4; jj++)
            LDM4(bf[jj], smB + (wm * 64 + jj * 16 + rsel) * ROW2B + ks * 32 + csel);
        #pragma unroll
        for (int t = 0; t < 2; t++)
            #pragma unroll
            for (int j = 0; j < 8; j++)
                MMA(acc[t][j], af[t], bf[j >> 1][(j & 1)], bf[j >> 1][(j & 1) + 2]);
    }
}

// ---------------- GEMM1: Y1[n][m] = sum_k X1[n,k]*W1s[m,k]; BK=64, 2-stage ----------------
__global__ __launch_bounds__(256, 2) void gemm1_tc() {
    extern __shared__ char dsm[];
    uint32_t sb = smem_u32(dsm);
    int tid = threadIdx.x, lane = tid & 31, wid = tid >> 5;
    int wn = wid & 3, wm = wid >> 2;
    int m0 = blockIdx.x * 128, n0 = blockIdx.y * 128;   // x fastest -> m-pair shares n-tile in L2

    const __nv_bfloat16* Xb = g_X1  + (size_t)n0 * X1ROW;
    const __nv_bfloat16* Wb = g_W1s + (size_t)m0 * W1ROW;

    float acc[2][8][4];
    #pragma unroll
    for (int t = 0; t < 2; t++)
        #pragma unroll
        for (int j = 0; j < 8; j++)
            #pragma unroll
            for (int d = 0; d < 4; d++) acc[t][j][d] = 0.f;

    auto load = [&](int i) {
        int s = i & 1;
        int t = i / 6, kc = i % 6;
        int aoff = ((t == 1) ? 384 : 0) + kc * 64;   // X: lo half for term 1
        int boff = ((t == 2) ? 384 : 0) + kc * 64;   // W: lo half for term 2
        uint32_t dstA = sb + s * STAGE2B;
        uint32_t dstB = dstA + TILE2B;
        #pragma unroll
        for (int u = 0; u < 4; u++) {
            int f = tid + u * 256;
            int r = f >> 3, c16 = f & 7;
            CP16(dstA + r * ROW2B + c16 * 16, Xb + (size_t)r * X1ROW + aoff + c16 * 8);
            CP16(dstB + r * ROW2B + c16 * 16, Wb + (size_t)r * W1ROW + boff + c16 * 8);
        }
        CPCOMMIT();
    };

    load(0);
    for (int i = 0; i < 18; i++) {
        CPWAIT0();
        __syncthreads();
        if (i < 17) load(i + 1);
        int s = i & 1;
        mma_chunk64(sb + s * STAGE2B, sb + s * STAGE2B + TILE2B, wn, wm, lane, acc);
    }

    float* dst = g_Y1;
    #pragma unroll
    for (int t = 0; t < 2; t++) {
        #pragma unroll
        for (int j = 0; j < 8; j++) {
            int nr = n0 + wn * 32 + t * 16 + (lane >> 2);
            int mc = m0 + wm * 64 + j * 8 + (lane & 3) * 2;
            float2 v0 = make_float2(acc[t][j][0], acc[t][j][1]);
            float2 v1 = make_float2(acc[t][j][2], acc[t][j][3]);
            *(float2*)&dst[(size_t)nr * 256 + mc]       = v0;
            *(float2*)&dst[(size_t)(nr + 8) * 256 + mc] = v1;
        }
    }
    #pragma unroll
    for (int j = 0; j < 8; j++) {
        float s0 = 0.f, q0 = 0.f, s1 = 0.f, q1 = 0.f;
        #pragma unroll
        for (int t = 0; t < 2; t++) {
            s0 += acc[t][j][0] + acc[t][j][2];
            q0 += acc[t][j][0] * acc[t][j][0] + acc[t][j][2] * acc[t][j][2];
            s1 += acc[t][j][1] + acc[t][j][3];
            q1 += acc[t][j][1] * acc[t][j][1] + acc[t][j][3] * acc[t][j][3];
        }
        #pragma unroll
        for (int off = 4; off < 32; off <<= 1) {
            s0 += __shfl_xor_sync(0xffffffffu, s0, off);
            q0 += __shfl_xor_sync(0xffffffffu, q0, off);
            s1 += __shfl_xor_sync(0xffffffffu, s1, off);
            q1 += __shfl_xor_sync(0xffffffffu, q1, off);
        }
        if (lane < 4) {
            int mc = m0 + wm * 64 + j * 8 + lane * 2;
            atomicAdd(&g_sum1[mc], s0);  atomicAdd(&g_sq1[mc], q0);
            atomicAdd(&g_sum1[mc + 1], s1); atomicAdd(&g_sq1[mc + 1], q1);
        }
    }
}

// ---------------- finalize BN ----------------
__global__ void finalize1_kernel(const float* __restrict__ g1, const float* __restrict__ be1) {
    int i = threadIdx.x;
    float mean = g_sum1[i] * (1.0f / NTOT);
    float var  = g_sq1[i] * (1.0f / NTOT) - mean * mean;
    float sc   = g1[i] * rsqrtf(var + EPS_BN);
    g_scale1[i] = sc;
    g_shift1[i] = be1[i] - mean * sc;
}
__global__ void finalize2_kernel(const float* __restrict__ g2, const float* __restrict__ be2) {
    int i = threadIdx.x;
    float mean = g_sum2[i] * (1.0f / NTOT);
    float var  = g_sq2[i] * (1.0f / NTOT) - mean * mean;
    float sc   = g2[i] * rsqrtf(var + EPS_BN);
    g_scale2[i] = sc;
    g_shift2[i] = be2[i] - mean * sc;
}

// ---------------- mid: X2 = hi/lo split of relu(BN1(Y1)) ----------------
__global__ void mid_kernel() {
    __shared__ float sc[M1], sh[M1];
    int tid = threadIdx.x;
    sc[tid] = g_scale1[tid]; sh[tid] = g_shift1[tid];
    __syncthreads();
    int i4 = blockIdx.x * 256 + tid;
    int n = i4 >> 6, c = (i4 & 63) * 4;
    float4 v = *(const float4*)&g_Y1[(size_t)n * 256 + c];
    float y0 = fmaxf(fmaf(sc[c + 0], v.x, sh[c + 0]), 0.f);
    float y1 = fmaxf(fmaf(sc[c + 1], v.y, sh[c + 1]), 0.f);
    float y2 = fmaxf(fmaf(sc[c + 2], v.z, sh[c + 2]), 0.f);
    float y3 = fmaxf(fmaf(sc[c + 3], v.w, sh[c + 3]), 0.f);
    __nv_bfloat16 h0 = bhi(y0), h1 = bhi(y1), h2 = bhi(y2), h3 = bhi(y3);
    size_t row = (size_t)n * X2ROW;
    __nv_bfloat162 o;
    o.x = h0; o.y = h1; *(__nv_bfloat162*)&g_X2[row + c] = o;
    o.x = h2; o.y = h3; *(__nv_bfloat162*)&g_X2[row + c + 2] = o;
    o.x = blo(y0, h0); o.y = blo(y1, h1); *(__nv_bfloat162*)&g_X2[row + 256 + c] = o;
    o.x = blo(y2, h2); o.y = blo(y3, h3); *(__nv_bfloat162*)&g_X2[row + 256 + c + 2] = o;
}

// ---------------- GEMM2: out = W2s @ X2 (HMMA), BK=64, 2-stage + 2-pass epilogue ----------------
__global__ __launch_bounds__(256, 2) void gemm2_tc(float* __restrict__ out) {
    extern __shared__ char dsm[];
    uint32_t sb = smem_u32(dsm);
    int tid = threadIdx.x, lane = tid & 31, wid = tid >> 5;
    int wn = wid & 3, wm = wid >> 2;
    int n0 = blockIdx.x * 128;

    const __nv_bfloat16* Xb = g_X2 + (size_t)n0 * X2ROW;
    const __nv_bfloat16* Wb = g_W2s;

    float acc[2][8][4];
    #pragma unroll
    for (int t = 0; t < 2; t++)
        #pragma unroll
        for (int j = 0; j < 8; j++)
            #pragma unroll
            for (int d = 0; d < 4; d++) acc[t][j][d] = 0.f;

    auto load = [&](int i) {
        int s = i & 1;
        int t = i / 4, kc = i % 4;
        int aoff = ((t == 1) ? 256 : 0) + kc * 64;
        int boff = ((t == 2) ? 256 : 0) + kc * 64;
        uint32_t dstA = sb + s * STAGE2B;
        uint32_t dstB = dstA + TILE2B;
        #pragma unroll
        for (int u = 0; u < 4; u++) {
            int f = tid + u * 256;
            int r = f >> 3, c16 = f & 7;
            CP16(dstA + r * ROW2B + c16 * 16, Xb + (size_t)r * X2ROW + aoff + c16 * 8);
            CP16(dstB + r * ROW2B + c16 * 16, Wb + (size_t)r * W2ROW + boff + c16 * 8);
        }
        CPCOMMIT();
    };

    load(0);
    for (int i = 0; i < 12; i++) {
        CPWAIT0();
        __syncthreads();
        if (i < 11) load(i + 1);
        int s = i & 1;
        mma_chunk64(sb + s * STAGE2B, sb + s * STAGE2B + TILE2B, wn, wm, lane, acc);
    }

    // epilogue: two 64-channel passes through smem
    float* smT = (float*)dsm;
    int b = n0 >> 14, nn = n0 & (N1 - 1);
    #pragma unroll
    for (int h = 0; h < 2; h++) {
        __syncthreads();
        if (wm == h) {
            #pragma unroll
            for (int t = 0; t < 2; t++)
                #pragma unroll
                for (int j = 0; j < 8; j++) {
                    int nr = wn * 32 + t * 16 + (lane >> 2);
                    int ml = j * 8 + (lane & 3) * 2;
                    smT[(ml)     * 136 + nr]     = acc[t][j][0];
                    smT[(ml + 1) * 136 + nr]     = acc[t][j][1];
                    smT[(ml)     * 136 + nr + 8] = acc[t][j][2];
                    smT[(ml + 1) * 136 + nr + 8] = acc[t][j][3];
                }
        }
        __syncthreads();
        for (int m = wid; m < 64; m += 8) {
            float4 v = *(float4*)&smT[m * 136 + lane * 4];
            *(float4*)&out[((size_t)b * M2 + h * 64 + m) * N1 + nn + lane * 4] = v;
        }
    }
    // BN2 stats
    #pragma unroll
    for (int j = 0; j < 8; j++) {
        float s0 = 0.f, q0 = 0.f, s1 = 0.f, q1 = 0.f;
        #pragma unroll
        for (int t = 0; t < 2; t++) {
            s0 += acc[t][j][0] + acc[t][j][2];
            q0 += acc[t][j][0] * acc[t][j][0] + acc[t][j][2] * acc[t][j][2];
            s1 += acc[t][j][1] + acc[t][j][3];
            q1 += acc[t][j][1] * acc[t][j][1] + acc[t][j][3] * acc[t][j][3];
        }
        #pragma unroll
        for (int off = 4; off < 32; off <<= 1) {
            s0 += __shfl_xor_sync(0xffffffffu, s0, off);
            q0 += __shfl_xor_sync(0xffffffffu, q0, off);
            s1 += __shfl_xor_sync(0xffffffffu, s1, off);
            q1 += __shfl_xor_sync(0xffffffffu, q1, off);
        }
        if (lane < 4) {
            int mc = wm * 64 + j * 8 + lane * 2;
            atomicAdd(&g_sum2[mc], s0);  atomicAdd(&g_sq2[mc], q0);
            atomicAdd(&g_sum2[mc + 1], s1); atomicAdd(&g_sq2[mc + 1], q1);
        }
    }
}

// ---------------- final BN2 + relu in place ----------------
__global__ void bn2_kernel(float* __restrict__ out) {
    int i4 = blockIdx.x * 256 + threadIdx.x;
    int m  = (i4 >> 12) & 127;
    float s = g_scale2[m], t = g_shift2[m];
    float4 v = ((float4*)out)[i4];
    v.x = fmaxf(fmaf(s, v.x, t), 0.f);
    v.y = fmaxf(fmaf(s, v.y, t), 0.f);
    v.z = fmaxf(fmaf(s, v.z, t), 0.f);
    v.w = fmaxf(fmaf(s, v.w, t), 0.f);
    ((float4*)out)[i4] = v;
}

// ---------------- launcher ----------------
extern "C" void kernel_launch(void* const* d_in, const int* in_sizes, int n_in,
                              void* d_out, int out_size) {
    const float* xyz1    = (const float*)d_in[0];
    const float* xyz2    = (const float*)d_in[1];
    const float* points1 = (const float*)d_in[2];
    const float* points2 = (const float*)d_in[3];
    const float* W1      = (const float*)d_in[4];
    const float* g1      = (const float*)d_in[6];
    const float* be1     = (const float*)d_in[7];
    const float* W2      = (const float*)d_in[8];
    const float* g2      = (const float*)d_in[10];
    const float* be2     = (const float*)d_in[11];
    float* out = (float*)d_out;

    cudaFuncSetAttribute(gemm1_tc, cudaFuncAttributeMaxDynamicSharedMemorySize, SMEM_DYN);
    cudaFuncSetAttribute(gemm2_tc, cudaFuncAttributeMaxDynamicSharedMemorySize, SMEM_DYN);

    init_kernel<<<1, 256>>>();
    transpose_p2_kernel<<<dim3(N2 / 32, C2 / 32, BB), dim3(32, 8)>>>(points2);
    cvt_w_kernel<<<(M1 * 384) / 256, 256>>>(W1, W2);
    knn_kernel<<<dim3(N1 / 256, 4, BB), 256>>>(xyz1, xyz2);
    knn_merge_kernel<<<NTOT / 256, 256>>>(xyz1, xyz2);
    cvt_p1_kernel<<<dim3(N1 / 32, C1 / 32, BB), 256>>>(points1);
    interp_kernel<<<NTOT / 8, 256>>>();
    gemm1_tc<<<dim3(2, NTOT / 128), 256, SMEM_DYN>>>();
    finalize1_kernel<<<1, M1>>>(g1, be1);
    mid_kernel<<<(NTOT * 64) / 256, 256>>>();
    gemm2_tc<<<dim3(NTOT / 128, 1), 256, SMEM_DYN>>>(out);
    finalize2_kernel<<<1, M2>>>(g2, be2);
    bn2_kernel<<<(NTOT * M2 / 4) / 256, 256>>>(out);
}